// round 4
// baseline (speedup 1.0000x reference)
#include <cuda_runtime.h>
#include <math.h>
#include <stdint.h>

#define HQn 16
#define HKn 4
#define Dn 64
#define GATE_CHn 12
#define WINDOWn 1024
#define Bn 2
#define Tn 2048
#define En 1024
#define Fn 1536
#define Mn 4096

// Scratch (allocation-free rule: device globals)
__device__ __align__(256) float g_qkv[(size_t)Mn * Fn];
__device__ __align__(256) float g_att[(size_t)Mn * En];

// ---------------------------------------------------------------------------
// TF32 helpers
// ---------------------------------------------------------------------------
__device__ __forceinline__ uint32_t f2tf32(float x) {
    uint32_t r;
    asm("cvt.rna.tf32.f32 %0, %1;" : "=r"(r) : "f"(x));
    return r;
}

__device__ __forceinline__ void mma_tf32(float* d, const uint32_t* a,
                                         const uint32_t* b) {
    asm volatile(
        "mma.sync.aligned.m16n8k8.row.col.f32.tf32.tf32.f32 "
        "{%0,%1,%2,%3}, {%4,%5,%6,%7}, {%8,%9}, {%0,%1,%2,%3};\n"
        : "+f"(d[0]), "+f"(d[1]), "+f"(d[2]), "+f"(d[3])
        : "r"(a[0]), "r"(a[1]), "r"(a[2]), "r"(a[3]), "r"(b[0]), "r"(b[1]));
}

// ---------------------------------------------------------------------------
// TF32 tensor-core GEMM: C[M,N] = A[M,K] * B[N,K]^T (both K contiguous)
// ---------------------------------------------------------------------------
#define BKg 32
__global__ __launch_bounds__(256) void gemm_tf32(
    const float* __restrict__ A, const float* __restrict__ Bm,
    float* __restrict__ C, int M, int N, int K)
{
    __shared__ uint32_t As[BKg][136];
    __shared__ uint32_t Bs[BKg][136];

    const int tid = threadIdx.x;
    const int lane = tid & 31;
    const int warp = tid >> 5;
    const int wm = (warp & 3) * 32;
    const int wn = (warp >> 2) * 64;
    const int bm = blockIdx.y * 128;
    const int bn = blockIdx.x * 128;

    const int lm = tid & 127;
    const int lk = (tid >> 7) * 4;

    float acc[2][8][4];
    #pragma unroll
    for (int mt = 0; mt < 2; mt++)
        #pragma unroll
        for (int nt = 0; nt < 8; nt++)
            #pragma unroll
            for (int i = 0; i < 4; i++) acc[mt][nt][i] = 0.f;

    const float* Ap = A + (size_t)(bm + lm) * K + lk;
    const float* Bp = Bm + (size_t)(bn + lm) * K + lk;

    for (int k0 = 0; k0 < K; k0 += BKg) {
        #pragma unroll
        for (int kk = 0; kk < BKg; kk += 8) {
            float4 av = *(const float4*)(Ap + k0 + kk);
            float4 bv = *(const float4*)(Bp + k0 + kk);
            int kr = kk + lk;
            As[kr + 0][lm] = f2tf32(av.x);
            As[kr + 1][lm] = f2tf32(av.y);
            As[kr + 2][lm] = f2tf32(av.z);
            As[kr + 3][lm] = f2tf32(av.w);
            Bs[kr + 0][lm] = f2tf32(bv.x);
            Bs[kr + 1][lm] = f2tf32(bv.y);
            Bs[kr + 2][lm] = f2tf32(bv.z);
            Bs[kr + 3][lm] = f2tf32(bv.w);
        }
        __syncthreads();

        #pragma unroll
        for (int ks = 0; ks < BKg; ks += 8) {
            uint32_t afr[2][4], bfr[8][2];
            const int kk = ks + (lane & 3);
            #pragma unroll
            for (int mt = 0; mt < 2; mt++) {
                int m = wm + mt * 16 + (lane >> 2);
                afr[mt][0] = As[kk][m];
                afr[mt][1] = As[kk][m + 8];
                afr[mt][2] = As[kk + 4][m];
                afr[mt][3] = As[kk + 4][m + 8];
            }
            #pragma unroll
            for (int nt = 0; nt < 8; nt++) {
                int n = wn + nt * 8 + (lane >> 2);
                bfr[nt][0] = Bs[kk][n];
                bfr[nt][1] = Bs[kk + 4][n];
            }
            #pragma unroll
            for (int mt = 0; mt < 2; mt++)
                #pragma unroll
                for (int nt = 0; nt < 8; nt++)
                    mma_tf32(acc[mt][nt], afr[mt], bfr[nt]);
        }
        __syncthreads();
    }

    #pragma unroll
    for (int mt = 0; mt < 2; mt++) {
        const int r0 = bm + wm + mt * 16 + (lane >> 2);
        #pragma unroll
        for (int nt = 0; nt < 8; nt++) {
            const int c0 = bn + wn + nt * 8 + 2 * (lane & 3);
            *(float2*)(C + (size_t)r0 * N + c0) =
                make_float2(acc[mt][nt][0], acc[mt][nt][1]);
            *(float2*)(C + (size_t)(r0 + 8) * N + c0) =
                make_float2(acc[mt][nt][2], acc[mt][nt][3]);
        }
    }
}

// ---------------------------------------------------------------------------
// Fused gate + value_embeds mix, RoPE + RMSNorm (in place on g_qkv).
// ---------------------------------------------------------------------------
__global__ __launch_bounds__(128) void rope_rms_gate(
    float* __restrict__ qkv, const float* __restrict__ x,
    const float* __restrict__ ve, const float* __restrict__ rc,
    const float* __restrict__ rs, const float* __restrict__ wg)
{
    const int row = blockIdx.x;
    const int t = row & (Tn - 1);
    const int warp = threadIdx.x >> 5;
    const int lane = threadIdx.x & 31;

    for (int head = warp; head < HQn + 2 * HKn; head += 4) {
        float* p = qkv + (size_t)row * Fn + head * Dn;
        if (head < HQn + HKn) {
            float x1 = p[lane], x2 = p[lane + 32];
            float c = rc[t * (Dn / 2) + lane];
            float s = rs[t * (Dn / 2) + lane];
            float y1 = x1 * c - x2 * s;
            float y2 = x1 * s + x2 * c;
            float ss = y1 * y1 + y2 * y2;
            #pragma unroll
            for (int o = 16; o; o >>= 1) ss += __shfl_xor_sync(0xffffffffu, ss, o);
            float r = rsqrtf(ss * (1.0f / Dn) + 1e-8f);
            p[lane] = y1 * r;
            p[lane + 32] = y2 * r;
        } else {
            int hv = head - HQn - HKn;
            float pr = (lane < GATE_CHn)
                         ? x[(size_t)row * En + lane] * wg[hv * GATE_CHn + lane]
                         : 0.f;
            #pragma unroll
            for (int o = 16; o; o >>= 1) pr += __shfl_xor_sync(0xffffffffu, pr, o);
            float gate = 3.0f / (1.0f + __expf(-pr));
            const float* vp = ve + (size_t)row * (HKn * Dn) + hv * Dn;
            p[lane]      += gate * vp[lane];
            p[lane + 32] += gate * vp[lane + 32];
        }
    }
}

// ---------------------------------------------------------------------------
// Tensor-core flash attention (tf32 m16n8k8).
// QTILE=128 (8 warps x 16 rows), KTILE=64. Q split hi/lo for precision.
// Layouts (row-major, padded): Qhi/Qlo [128][68], K [64][68], V [64][72],
// P [128][72]. All fragment LDS patterns conflict-free by pad choice.
// ---------------------------------------------------------------------------
#define QTILE 128
#define KTILE 64
#define QP 68
#define KP 68
#define VP 72
#define PP 72

#define W_QHI 0
#define W_QLO (W_QHI + QTILE * QP)
#define W_KS  (W_QLO + QTILE * QP)
#define W_VS  (W_KS + KTILE * KP)
#define W_PS  (W_VS + KTILE * VP)
#define ATTN_WORDS (W_PS + QTILE * PP)
#define ATTN_SMEM_BYTES (ATTN_WORDS * 4)

__global__ __launch_bounds__(256) void attn_tc(
    const float* __restrict__ qkv, float* __restrict__ out)
{
    extern __shared__ uint32_t sm[];
    uint32_t* Qh = sm + W_QHI;
    uint32_t* Ql = sm + W_QLO;
    uint32_t* Ks = sm + W_KS;
    uint32_t* Vs = sm + W_VS;
    uint32_t* Ps = sm + W_PS;

    const int tid = threadIdx.x;
    const int lane = tid & 31;
    const int warp = tid >> 5;
    const int q0 = blockIdx.x * QTILE;
    const int h  = blockIdx.y;
    const int bb = blockIdx.z;
    const int hk = h >> 2;
    const int qoff = h * Dn;
    const int koff = (HQn + hk) * Dn;
    const int voff = (HQn + HKn + hk) * Dn;
    const int row0 = bb * Tn + q0;

    const int lq = lane >> 2;       // 0..7  (row within m16 half / n index)
    const int lc = lane & 3;        // 0..3  (k index within frag)
    const int rA = warp * 16 + lq;  // this thread's base row in the q tile

    // ---- load Q tile, split hi/lo tf32 ----
    #pragma unroll
    for (int it = 0; it < 8; it++) {
        int f = tid + 256 * it;
        int r = f >> 4, c = (f & 15) * 4;
        float4 v = *(const float4*)(qkv + (size_t)(row0 + r) * Fn + qoff + c);
        float q[4] = {v.x * 0.125f, v.y * 0.125f, v.z * 0.125f, v.w * 0.125f};
        #pragma unroll
        for (int i = 0; i < 4; i++) {
            uint32_t hi = f2tf32(q[i]);
            Qh[r * QP + c + i] = hi;
            Ql[r * QP + c + i] = f2tf32(q[i] - __uint_as_float(hi));
        }
    }

    float o[8][4];
    float m_s[2] = {-1e30f, -1e30f};
    float l_s[2] = {0.f, 0.f};
    #pragma unroll
    for (int nt = 0; nt < 8; nt++)
        #pragma unroll
        for (int e = 0; e < 4; e++) o[nt][e] = 0.f;

    const int kt_lo = (q0 > WINDOWn) ? ((q0 - WINDOWn) >> 6) : 0;
    const int kt_hi = (q0 + QTILE - 1) >> 6;

    for (int kt = kt_lo; kt <= kt_hi; kt++) {
        const int k0 = kt * KTILE;
        const int krow0 = bb * Tn + k0;
        __syncthreads();   // protect K/V/P from previous iteration's readers
        #pragma unroll
        for (int it = 0; it < 4; it++) {
            int f = tid + 256 * it;
            int r = f >> 4, c = (f & 15) * 4;
            float4 kv = *(const float4*)(qkv + (size_t)(krow0 + r) * Fn + koff + c);
            float4 vv = *(const float4*)(qkv + (size_t)(krow0 + r) * Fn + voff + c);
            Ks[r * KP + c + 0] = f2tf32(kv.x);
            Ks[r * KP + c + 1] = f2tf32(kv.y);
            Ks[r * KP + c + 2] = f2tf32(kv.z);
            Ks[r * KP + c + 3] = f2tf32(kv.w);
            Vs[r * VP + c + 0] = f2tf32(vv.x);
            Vs[r * VP + c + 1] = f2tf32(vv.y);
            Vs[r * VP + c + 2] = f2tf32(vv.z);
            Vs[r * VP + c + 3] = f2tf32(vv.w);
        }
        __syncthreads();

        // ---- S = Q K^T (warp: 16 rows x 64 keys) ----
        float s[8][4];
        #pragma unroll
        for (int nt = 0; nt < 8; nt++)
            #pragma unroll
            for (int e = 0; e < 4; e++) s[nt][e] = 0.f;

        #pragma unroll
        for (int ks = 0; ks < 8; ks++) {
            const int kk = ks * 8 + lc;
            uint32_t ah[4], al[4];
            ah[0] = Qh[rA * QP + kk];
            ah[1] = Qh[(rA + 8) * QP + kk];
            ah[2] = Qh[rA * QP + kk + 4];
            ah[3] = Qh[(rA + 8) * QP + kk + 4];
            al[0] = Ql[rA * QP + kk];
            al[1] = Ql[(rA + 8) * QP + kk];
            al[2] = Ql[rA * QP + kk + 4];
            al[3] = Ql[(rA + 8) * QP + kk + 4];
            #pragma unroll
            for (int nt = 0; nt < 8; nt++) {
                const int key = nt * 8 + lq;
                uint32_t b[2];
                b[0] = Ks[key * KP + kk];
                b[1] = Ks[key * KP + kk + 4];
                mma_tf32(s[nt], ah, b);
                mma_tf32(s[nt], al, b);
            }
        }

        // ---- mask ----
        const bool full_live = (k0 + KTILE - 1 <= q0) &&
                               (k0 >= q0 + QTILE - 1 - WINDOWn);
        if (!full_live) {
            #pragma unroll
            for (int nt = 0; nt < 8; nt++)
                #pragma unroll
                for (int e = 0; e < 4; e++) {
                    int i = q0 + rA + ((e >= 2) ? 8 : 0);
                    int j = k0 + nt * 8 + 2 * lc + (e & 1);
                    if (j > i || j + WINDOWn < i) s[nt][e] = -1e30f;
                }
        }

        // ---- online softmax (rows rA and rA+8) ----
        float ma = -1e30f, mb = -1e30f;
        #pragma unroll
        for (int nt = 0; nt < 8; nt++) {
            ma = fmaxf(ma, fmaxf(s[nt][0], s[nt][1]));
            mb = fmaxf(mb, fmaxf(s[nt][2], s[nt][3]));
        }
        ma = fmaxf(ma, __shfl_xor_sync(0xffffffffu, ma, 1));
        ma = fmaxf(ma, __shfl_xor_sync(0xffffffffu, ma, 2));
        mb = fmaxf(mb, __shfl_xor_sync(0xffffffffu, mb, 1));
        mb = fmaxf(mb, __shfl_xor_sync(0xffffffffu, mb, 2));

        float mnA = fmaxf(m_s[0], ma), mnB = fmaxf(m_s[1], mb);
        float alA = __expf(m_s[0] - mnA), alB = __expf(m_s[1] - mnB);
        m_s[0] = mnA; m_s[1] = mnB;
        const bool liveA = mnA > -1e29f, liveB = mnB > -1e29f;

        float sumA = 0.f, sumB = 0.f;
        #pragma unroll
        for (int nt = 0; nt < 8; nt++) {
            float p0 = liveA ? __expf(s[nt][0] - mnA) : 0.f;
            float p1 = liveA ? __expf(s[nt][1] - mnA) : 0.f;
            float p2 = liveB ? __expf(s[nt][2] - mnB) : 0.f;
            float p3 = liveB ? __expf(s[nt][3] - mnB) : 0.f;
            sumA += p0 + p1;
            sumB += p2 + p3;
            *(uint2*)&Ps[rA * PP + nt * 8 + 2 * lc] =
                make_uint2(f2tf32(p0), f2tf32(p1));
            *(uint2*)&Ps[(rA + 8) * PP + nt * 8 + 2 * lc] =
                make_uint2(f2tf32(p2), f2tf32(p3));
        }
        sumA += __shfl_xor_sync(0xffffffffu, sumA, 1);
        sumA += __shfl_xor_sync(0xffffffffu, sumA, 2);
        sumB += __shfl_xor_sync(0xffffffffu, sumB, 1);
        sumB += __shfl_xor_sync(0xffffffffu, sumB, 2);
        l_s[0] = l_s[0] * alA + sumA;
        l_s[1] = l_s[1] * alB + sumB;
        #pragma unroll
        for (int nt = 0; nt < 8; nt++) {
            o[nt][0] *= alA; o[nt][1] *= alA;
            o[nt][2] *= alB; o[nt][3] *= alB;
        }
        __syncwarp();   // P visible within warp (warp reads only its own rows)

        // ---- O += P V (warp: 16 rows x 64 d, K=64 keys) ----
        #pragma unroll
        for (int ks = 0; ks < 8; ks++) {
            const int kp = ks * 8 + lc;
            uint32_t a[4];
            a[0] = Ps[rA * PP + kp];
            a[1] = Ps[(rA + 8) * PP + kp];
            a[2] = Ps[rA * PP + kp + 4];
            a[3] = Ps[(rA + 8) * PP + kp + 4];
            #pragma unroll
            for (int nt = 0; nt < 8; nt++) {
                const int d = nt * 8 + lq;
                uint32_t b[2];
                b[0] = Vs[kp * VP + d];
                b[1] = Vs[(kp + 4) * VP + d];
                mma_tf32(o[nt], a, b);
            }
        }
    }

    // ---- normalize + store ----
    const float invA = 1.0f / l_s[0];
    const float invB = 1.0f / l_s[1];
    #pragma unroll
    for (int nt = 0; nt < 8; nt++) {
        const int c0 = qoff + nt * 8 + 2 * lc;
        *(float2*)(out + (size_t)(row0 + rA) * En + c0) =
            make_float2(o[nt][0] * invA, o[nt][1] * invA);
        *(float2*)(out + (size_t)(row0 + rA + 8) * En + c0) =
            make_float2(o[nt][2] * invB, o[nt][3] * invB);
    }
}

// ---------------------------------------------------------------------------
extern "C" void kernel_launch(void* const* d_in, const int* in_sizes, int n_in,
                              void* d_out, int out_size)
{
    (void)in_sizes; (void)n_in; (void)out_size;
    const float* x    = (const float*)d_in[0];
    const float* ve   = (const float*)d_in[1];
    const float* rc   = (const float*)d_in[2];
    const float* rs   = (const float*)d_in[3];
    const float* wqkv = (const float*)d_in[4];
    const float* wg   = (const float*)d_in[5];
    const float* wo   = (const float*)d_in[6];
    float* out = (float*)d_out;

    float *qkv_p = nullptr, *att_p = nullptr;
    cudaGetSymbolAddress((void**)&qkv_p, g_qkv);
    cudaGetSymbolAddress((void**)&att_p, g_att);

    cudaFuncSetAttribute(attn_tc,
                         cudaFuncAttributeMaxDynamicSharedMemorySize,
                         ATTN_SMEM_BYTES);

    gemm_tf32<<<dim3(Fn / 128, Mn / 128), 256>>>(x, wqkv, qkv_p, Mn, Fn, En);
    rope_rms_gate<<<Mn, 128>>>(qkv_p, x, ve, rc, rs, wg);
    attn_tc<<<dim3(Tn / QTILE, HQn, Bn), 256, ATTN_SMEM_BYTES>>>(qkv_p, att_p);
    gemm_tf32<<<dim3(En / 128, Mn / 128), 256>>>(att_p, wo, out, Mn, En, En);
}

// round 5
// speedup vs baseline: 1.2485x; 1.2485x over previous
#include <cuda_runtime.h>
#include <math.h>
#include <stdint.h>

#define HQn 16
#define HKn 4
#define Dn 64
#define GATE_CHn 12
#define WINDOWn 1024
#define Bn 2
#define Tn 2048
#define En 1024
#define Fn 1536
#define Mn 4096

// Scratch (allocation-free rule: device globals)
__device__ __align__(256) float g_qkv[(size_t)Mn * Fn];
__device__ __align__(256) float g_att[(size_t)Mn * En];

// ---------------------------------------------------------------------------
// TF32 helpers
// ---------------------------------------------------------------------------
__device__ __forceinline__ uint32_t f2tf32(float x) {
    uint32_t r;
    asm("cvt.rna.tf32.f32 %0, %1;" : "=r"(r) : "f"(x));
    return r;
}

__device__ __forceinline__ void mma_tf32(float* d, const uint32_t* a,
                                         const uint32_t* b) {
    asm volatile(
        "mma.sync.aligned.m16n8k8.row.col.f32.tf32.tf32.f32 "
        "{%0,%1,%2,%3}, {%4,%5,%6,%7}, {%8,%9}, {%0,%1,%2,%3};\n"
        : "+f"(d[0]), "+f"(d[1]), "+f"(d[2]), "+f"(d[3])
        : "r"(a[0]), "r"(a[1]), "r"(a[2]), "r"(a[3]), "r"(b[0]), "r"(b[1]));
}

// ---------------------------------------------------------------------------
// TF32 GEMM: C[M,N] = A[M,K] * B[N,K]^T, permuted-swizzled smem (LDS.128
// fragment loads, conflict-free stores/loads). 128x128 tile, BK=32, 8 warps.
// Smem word (row, k) -> row*36 + ((perm32(k)) ^ (((row>>3)&3)<<3)),
// perm32(k) = (k&3)*8 + (k>>2): thread's k-run lc+4j is contiguous.
// ---------------------------------------------------------------------------
#define BKg 32
__global__ __launch_bounds__(256, 2) void gemm_tf32(
    const float* __restrict__ A, const float* __restrict__ Bm,
    float* __restrict__ C, int M, int N, int K)
{
    __shared__ uint32_t As[128 * 36];
    __shared__ uint32_t Bs[128 * 36];

    const int tid = threadIdx.x;
    const int lane = tid & 31;
    const int warp = tid >> 5;
    const int wm = (warp & 3) * 32;
    const int wn = (warp >> 2) * 64;
    const int bm = blockIdx.y * 128;
    const int bn = blockIdx.x * 128;
    const int lq = lane >> 2;
    const int lc = lane & 3;

    const int lm = tid & 127;
    const int lk = (tid >> 7) * 4;
    const int ssw = (lm >> 3) & 3;   // store swizzle for this loader row

    float acc[2][8][4];
    #pragma unroll
    for (int mt = 0; mt < 2; mt++)
        #pragma unroll
        for (int nt = 0; nt < 8; nt++)
            #pragma unroll
            for (int i = 0; i < 4; i++) acc[mt][nt][i] = 0.f;

    const float* Ap = A + (size_t)(bm + lm) * K + lk;
    const float* Bp = Bm + (size_t)(bn + lm) * K + lk;

    for (int k0 = 0; k0 < K; k0 += BKg) {
        #pragma unroll
        for (int kk = 0; kk < BKg; kk += 8) {
            float4 av = *(const float4*)(Ap + k0 + kk);
            float4 bv = *(const float4*)(Bp + k0 + kk);
            const int kr = kk + lk;
            const int c = kr >> 2;
            uint32_t* pa = &As[lm * 36 + c];
            uint32_t* pb = &Bs[lm * 36 + c];
            pa[(0 ^ ssw) << 3] = f2tf32(av.x);
            pa[(1 ^ ssw) << 3] = f2tf32(av.y);
            pa[(2 ^ ssw) << 3] = f2tf32(av.z);
            pa[(3 ^ ssw) << 3] = f2tf32(av.w);
            pb[(0 ^ ssw) << 3] = f2tf32(bv.x);
            pb[(1 ^ ssw) << 3] = f2tf32(bv.y);
            pb[(2 ^ ssw) << 3] = f2tf32(bv.z);
            pb[(3 ^ ssw) << 3] = f2tf32(bv.w);
        }
        __syncthreads();

        // a fragments: rows wm + lq + {0,8,16,24}, all BK=32 k (8 words each)
        uint32_t a_all[4][8];
        #pragma unroll
        for (int r = 0; r < 4; r++) {
            const int m = wm + lq + r * 8;
            const uint32_t* p = &As[m * 36 + ((lc ^ ((m >> 3) & 3)) << 3)];
            *(uint4*)&a_all[r][0] = *(const uint4*)p;
            *(uint4*)&a_all[r][4] = *(const uint4*)(p + 4);
        }
        #pragma unroll
        for (int nt = 0; nt < 8; nt++) {
            const int n = wn + nt * 8 + lq;
            const uint32_t* p = &Bs[n * 36 + ((lc ^ ((n >> 3) & 3)) << 3)];
            uint32_t bb[8];
            *(uint4*)&bb[0] = *(const uint4*)p;
            *(uint4*)&bb[4] = *(const uint4*)(p + 4);
            #pragma unroll
            for (int ks = 0; ks < 4; ks++) {
                uint32_t af0[4] = {a_all[0][2 * ks], a_all[1][2 * ks],
                                   a_all[0][2 * ks + 1], a_all[1][2 * ks + 1]};
                uint32_t af1[4] = {a_all[2][2 * ks], a_all[3][2 * ks],
                                   a_all[2][2 * ks + 1], a_all[3][2 * ks + 1]};
                uint32_t bf[2] = {bb[2 * ks], bb[2 * ks + 1]};
                mma_tf32(acc[0][nt], af0, bf);
                mma_tf32(acc[1][nt], af1, bf);
            }
        }
        __syncthreads();
    }

    #pragma unroll
    for (int mt = 0; mt < 2; mt++) {
        const int r0 = bm + wm + mt * 16 + lq;
        #pragma unroll
        for (int nt = 0; nt < 8; nt++) {
            const int c0 = bn + wn + nt * 8 + 2 * lc;
            *(float2*)(C + (size_t)r0 * N + c0) =
                make_float2(acc[mt][nt][0], acc[mt][nt][1]);
            *(float2*)(C + (size_t)(r0 + 8) * N + c0) =
                make_float2(acc[mt][nt][2], acc[mt][nt][3]);
        }
    }
}

// ---------------------------------------------------------------------------
// Fused gate + value_embeds mix, RoPE + RMSNorm (in place on g_qkv).
// ---------------------------------------------------------------------------
__global__ __launch_bounds__(128) void rope_rms_gate(
    float* __restrict__ qkv, const float* __restrict__ x,
    const float* __restrict__ ve, const float* __restrict__ rc,
    const float* __restrict__ rs, const float* __restrict__ wg)
{
    const int row = blockIdx.x;
    const int t = row & (Tn - 1);
    const int warp = threadIdx.x >> 5;
    const int lane = threadIdx.x & 31;

    for (int head = warp; head < HQn + 2 * HKn; head += 4) {
        float* p = qkv + (size_t)row * Fn + head * Dn;
        if (head < HQn + HKn) {
            float x1 = p[lane], x2 = p[lane + 32];
            float c = rc[t * (Dn / 2) + lane];
            float s = rs[t * (Dn / 2) + lane];
            float y1 = x1 * c - x2 * s;
            float y2 = x1 * s + x2 * c;
            float ss = y1 * y1 + y2 * y2;
            #pragma unroll
            for (int o = 16; o; o >>= 1) ss += __shfl_xor_sync(0xffffffffu, ss, o);
            float r = rsqrtf(ss * (1.0f / Dn) + 1e-8f);
            p[lane] = y1 * r;
            p[lane + 32] = y2 * r;
        } else {
            int hv = head - HQn - HKn;
            float pr = (lane < GATE_CHn)
                         ? x[(size_t)row * En + lane] * wg[hv * GATE_CHn + lane]
                         : 0.f;
            #pragma unroll
            for (int o = 16; o; o >>= 1) pr += __shfl_xor_sync(0xffffffffu, pr, o);
            float gate = 3.0f / (1.0f + __expf(-pr));
            const float* vp = ve + (size_t)row * (HKn * Dn) + hv * Dn;
            p[lane]      += gate * vp[lane];
            p[lane + 32] += gate * vp[lane + 32];
        }
    }
}

// ---------------------------------------------------------------------------
// Tensor-core flash attention v3.
//  - Q fragments in registers (loaded once), single tf32.
//  - K split hi/lo in smem (precision), permuted-swizzled: LDS.128 frags.
//  - Fixed-max softmax: rms-norm => |s|<=8 exactly, p = exp(s-8). No online
//    max, no rescaling.
//  - P permuted-swizzled (LDS.128 a-frags for PV).
// Smem: Khi[64*68] Klo[64*68] Vs[64*72] Ps[128*68] = 86 KB -> 2 CTAs/SM.
// perm64(k) = (k&3)*16 + (k>>2); swizzle XOR ((row>>3)&3)<<4.
// ---------------------------------------------------------------------------
#define QTILE 128
#define KTILE 64

#define W_KHI 0
#define W_KLO (W_KHI + 64 * 68)
#define W_VS  (W_KLO + 64 * 68)
#define W_PS  (W_VS + 64 * 72)
#define ATTN_WORDS (W_PS + QTILE * 68)
#define ATTN_SMEM_BYTES (ATTN_WORDS * 4)

__global__ __launch_bounds__(256, 2) void attn_tc(
    const float* __restrict__ qkv, float* __restrict__ out)
{
    extern __shared__ uint32_t sm[];
    uint32_t* Khi = sm + W_KHI;
    uint32_t* Klo = sm + W_KLO;
    uint32_t* Vs  = sm + W_VS;
    uint32_t* Ps  = sm + W_PS;

    const int tid = threadIdx.x;
    const int lane = tid & 31;
    const int warp = tid >> 5;
    const int q0 = blockIdx.x * QTILE;
    const int h  = blockIdx.y;
    const int bb = blockIdx.z;
    const int hk = h >> 2;
    const int qoff = h * Dn;
    const int koff = (HQn + hk) * Dn;
    const int voff = (HQn + HKn + hk) * Dn;
    const int row0 = bb * Tn + q0;

    const int lq = lane >> 2;
    const int lc = lane & 3;
    const int rA = warp * 16 + lq;

    // ---- Q fragments to registers (once). qA[j] <-> d = lc + 4j, row rA;
    //      qB row rA+8. Scaled by 1/8.
    uint32_t qA[16], qB[16];
    {
        const float* q0p = qkv + (size_t)(row0 + rA) * Fn + qoff + lc;
        const float* q1p = qkv + (size_t)(row0 + rA + 8) * Fn + qoff + lc;
        #pragma unroll
        for (int j = 0; j < 16; j++) {
            qA[j] = f2tf32(q0p[4 * j] * 0.125f);
            qB[j] = f2tf32(q1p[4 * j] * 0.125f);
        }
    }

    float o[8][4];
    #pragma unroll
    for (int nt = 0; nt < 8; nt++)
        #pragma unroll
        for (int e = 0; e < 4; e++) o[nt][e] = 0.f;
    float lA = 0.f, lB = 0.f;

    const int kt_lo = (q0 > WINDOWn) ? ((q0 - WINDOWn) >> 6) : 0;
    const int kt_hi = (q0 + QTILE - 1) >> 6;

    for (int kt = kt_lo; kt <= kt_hi; kt++) {
        const int k0 = kt * KTILE;
        const int krow0 = bb * Tn + k0;
        __syncthreads();  // previous tile fully consumed

        // ---- load K (hi/lo, permuted) and V (plain [k][d], pad 72)
        #pragma unroll
        for (int it = 0; it < 4; it++) {
            const int f = tid + 256 * it;
            const int r = f >> 4;
            const int c = (f & 15) * 4;
            float4 kv = *(const float4*)(qkv + (size_t)(krow0 + r) * Fn + koff + c);
            float4 vv = *(const float4*)(qkv + (size_t)(krow0 + r) * Fn + voff + c);
            const int sw = (r >> 3) & 3;
            uint32_t* ph = &Khi[r * 68 + (c >> 2)];
            uint32_t* pl = &Klo[r * 68 + (c >> 2)];
            float kk[4] = {kv.x, kv.y, kv.z, kv.w};
            #pragma unroll
            for (int i = 0; i < 4; i++) {
                uint32_t hi = f2tf32(kk[i]);
                ph[(i ^ sw) << 4] = hi;
                pl[(i ^ sw) << 4] = f2tf32(kk[i] - __uint_as_float(hi));
            }
            Vs[r * 72 + c + 0] = f2tf32(vv.x);
            Vs[r * 72 + c + 1] = f2tf32(vv.y);
            Vs[r * 72 + c + 2] = f2tf32(vv.z);
            Vs[r * 72 + c + 3] = f2tf32(vv.w);
        }
        __syncthreads();

        // ---- S + softmax + P store, per 8-key group (nt)
        #pragma unroll
        for (int nt = 0; nt < 8; nt++) {
            const int key = nt * 8 + lq;
            const uint32_t* pk = &Khi[key * 68 + ((lc ^ ((key >> 3) & 3)) << 4)];
            const uint32_t* pl = &Klo[key * 68 + ((lc ^ ((key >> 3) & 3)) << 4)];
            uint32_t kh[16], kl[16];
            *(uint4*)&kh[0]  = *(const uint4*)(pk + 0);
            *(uint4*)&kh[4]  = *(const uint4*)(pk + 4);
            *(uint4*)&kh[8]  = *(const uint4*)(pk + 8);
            *(uint4*)&kh[12] = *(const uint4*)(pk + 12);
            *(uint4*)&kl[0]  = *(const uint4*)(pl + 0);
            *(uint4*)&kl[4]  = *(const uint4*)(pl + 4);
            *(uint4*)&kl[8]  = *(const uint4*)(pl + 8);
            *(uint4*)&kl[12] = *(const uint4*)(pl + 12);

            float s[4] = {0.f, 0.f, 0.f, 0.f};
            #pragma unroll
            for (int ks = 0; ks < 8; ks++) {
                uint32_t af[4] = {qA[2 * ks], qB[2 * ks],
                                  qA[2 * ks + 1], qB[2 * ks + 1]};
                uint32_t bh[2] = {kh[2 * ks], kh[2 * ks + 1]};
                uint32_t bl[2] = {kl[2 * ks], kl[2 * ks + 1]};
                mma_tf32(s, af, bh);
                mma_tf32(s, af, bl);
            }

            // mask + fixed-max softmax: p = exp(s - 8), masked -> 0
            float p[4];
            #pragma unroll
            for (int e = 0; e < 4; e++) {
                const int i = q0 + rA + ((e >= 2) ? 8 : 0);
                const int j = k0 + nt * 8 + 2 * lc + (e & 1);
                const bool live = (j <= i) && (j + WINDOWn >= i);
                p[e] = live ? __expf(s[e] - 8.0f) : 0.f;
            }
            lA += p[0] + p[1];
            lB += p[2] + p[3];

            // store P (permuted layout on k index = column)
            #pragma unroll
            for (int e = 0; e < 4; e++) {
                const int col = nt * 8 + 2 * lc + (e & 1);
                const int pc = ((col & 3) << 4) | (col >> 2);
                const int row = rA + ((e >= 2) ? 8 : 0);
                Ps[row * 68 + (pc ^ (((row >> 3) & 3) << 4))] = f2tf32(p[e]);
            }
        }
        __syncwarp();  // P rows of this warp written by this warp only

        // ---- O += P V
        uint32_t pA[16], pB[16];
        {
            const uint32_t* p0 = &Ps[rA * 68 + ((lc ^ ((rA >> 3) & 3)) << 4)];
            const int rB = rA + 8;
            const uint32_t* p1 = &Ps[rB * 68 + ((lc ^ ((rB >> 3) & 3)) << 4)];
            *(uint4*)&pA[0]  = *(const uint4*)(p0 + 0);
            *(uint4*)&pA[4]  = *(const uint4*)(p0 + 4);
            *(uint4*)&pA[8]  = *(const uint4*)(p0 + 8);
            *(uint4*)&pA[12] = *(const uint4*)(p0 + 12);
            *(uint4*)&pB[0]  = *(const uint4*)(p1 + 0);
            *(uint4*)&pB[4]  = *(const uint4*)(p1 + 4);
            *(uint4*)&pB[8]  = *(const uint4*)(p1 + 8);
            *(uint4*)&pB[12] = *(const uint4*)(p1 + 12);
        }
        #pragma unroll
        for (int ks = 0; ks < 8; ks++) {
            const int kp = ks * 8 + lc;
            uint32_t af[4] = {pA[2 * ks], pB[2 * ks],
                              pA[2 * ks + 1], pB[2 * ks + 1]};
            #pragma unroll
            for (int nt = 0; nt < 8; nt++) {
                const int d = nt * 8 + lq;
                uint32_t bf[2] = {Vs[kp * 72 + d], Vs[(kp + 4) * 72 + d]};
                mma_tf32(o[nt], af, bf);
            }
        }
    }

    // ---- final l reduction across the 4 lanes of each row group
    lA += __shfl_xor_sync(0xffffffffu, lA, 1);
    lA += __shfl_xor_sync(0xffffffffu, lA, 2);
    lB += __shfl_xor_sync(0xffffffffu, lB, 1);
    lB += __shfl_xor_sync(0xffffffffu, lB, 2);
    const float invA = 1.0f / lA;
    const float invB = 1.0f / lB;

    #pragma unroll
    for (int nt = 0; nt < 8; nt++) {
        const int c0 = qoff + nt * 8 + 2 * lc;
        *(float2*)(out + (size_t)(row0 + rA) * En + c0) =
            make_float2(o[nt][0] * invA, o[nt][1] * invA);
        *(float2*)(out + (size_t)(row0 + rA + 8) * En + c0) =
            make_float2(o[nt][2] * invB, o[nt][3] * invB);
    }
}

// ---------------------------------------------------------------------------
extern "C" void kernel_launch(void* const* d_in, const int* in_sizes, int n_in,
                              void* d_out, int out_size)
{
    (void)in_sizes; (void)n_in; (void)out_size;
    const float* x    = (const float*)d_in[0];
    const float* ve   = (const float*)d_in[1];
    const float* rc   = (const float*)d_in[2];
    const float* rs   = (const float*)d_in[3];
    const float* wqkv = (const float*)d_in[4];
    const float* wg   = (const float*)d_in[5];
    const float* wo   = (const float*)d_in[6];
    float* out = (float*)d_out;

    float *qkv_p = nullptr, *att_p = nullptr;
    cudaGetSymbolAddress((void**)&qkv_p, g_qkv);
    cudaGetSymbolAddress((void**)&att_p, g_att);

    cudaFuncSetAttribute(attn_tc,
                         cudaFuncAttributeMaxDynamicSharedMemorySize,
                         ATTN_SMEM_BYTES);

    gemm_tf32<<<dim3(Fn / 128, Mn / 128), 256>>>(x, wqkv, qkv_p, Mn, Fn, En);
    rope_rms_gate<<<Mn, 128>>>(qkv_p, x, ve, rc, rs, wg);
    attn_tc<<<dim3(Tn / QTILE, HQn, Bn), 256, ATTN_SMEM_BYTES>>>(qkv_p, att_p);
    gemm_tf32<<<dim3(En / 128, Mn / 128), 256>>>(att_p, wo, out, Mn, En, En);
}

// round 6
// speedup vs baseline: 1.2600x; 1.0092x over previous
#include <cuda_runtime.h>
#include <math.h>
#include <stdint.h>

#define HQn 16
#define HKn 4
#define Dn 64
#define GATE_CHn 12
#define WINDOWn 1024
#define Bn 2
#define Tn 2048
#define En 1024
#define Fn 1536
#define Mn 4096

// Scratch (allocation-free rule: device globals)
__device__ __align__(256) float g_qkv[(size_t)Mn * Fn];
__device__ __align__(256) float g_att[(size_t)Mn * En];

// ---------------------------------------------------------------------------
// TF32 helpers
// ---------------------------------------------------------------------------
__device__ __forceinline__ uint32_t f2tf32(float x) {
    uint32_t r;
    asm("cvt.rna.tf32.f32 %0, %1;" : "=r"(r) : "f"(x));
    return r;
}

__device__ __forceinline__ void mma_tf32(float* d, const uint32_t* a,
                                         const uint32_t* b) {
    asm volatile(
        "mma.sync.aligned.m16n8k8.row.col.f32.tf32.tf32.f32 "
        "{%0,%1,%2,%3}, {%4,%5,%6,%7}, {%8,%9}, {%0,%1,%2,%3};\n"
        : "+f"(d[0]), "+f"(d[1]), "+f"(d[2]), "+f"(d[3])
        : "r"(a[0]), "r"(a[1]), "r"(a[2]), "r"(a[3]), "r"(b[0]), "r"(b[1]));
}

// ---------------------------------------------------------------------------
// TF32 GEMM: C[M,N] = A[M,K] * B[N,K]^T, permuted-swizzled smem, ILP-split
// MMA ordering (ks-outer over nt-pairs: same-acc reuse distance 4).
// ---------------------------------------------------------------------------
#define BKg 32
__global__ __launch_bounds__(256, 2) void gemm_tf32(
    const float* __restrict__ A, const float* __restrict__ Bm,
    float* __restrict__ C, int M, int N, int K)
{
    __shared__ uint32_t As[128 * 36];
    __shared__ uint32_t Bs[128 * 36];

    const int tid = threadIdx.x;
    const int lane = tid & 31;
    const int warp = tid >> 5;
    const int wm = (warp & 3) * 32;
    const int wn = (warp >> 2) * 64;
    const int bm = blockIdx.y * 128;
    const int bn = blockIdx.x * 128;
    const int lq = lane >> 2;
    const int lc = lane & 3;

    const int lm = tid & 127;
    const int lk = (tid >> 7) * 4;
    const int ssw = (lm >> 3) & 3;

    float acc[2][8][4];
    #pragma unroll
    for (int mt = 0; mt < 2; mt++)
        #pragma unroll
        for (int nt = 0; nt < 8; nt++)
            #pragma unroll
            for (int i = 0; i < 4; i++) acc[mt][nt][i] = 0.f;

    const float* Ap = A + (size_t)(bm + lm) * K + lk;
    const float* Bp = Bm + (size_t)(bn + lm) * K + lk;

    for (int k0 = 0; k0 < K; k0 += BKg) {
        #pragma unroll
        for (int kk = 0; kk < BKg; kk += 8) {
            float4 av = *(const float4*)(Ap + k0 + kk);
            float4 bv = *(const float4*)(Bp + k0 + kk);
            const int kr = kk + lk;
            const int c = kr >> 2;
            uint32_t* pa = &As[lm * 36 + c];
            uint32_t* pb = &Bs[lm * 36 + c];
            pa[(0 ^ ssw) << 3] = f2tf32(av.x);
            pa[(1 ^ ssw) << 3] = f2tf32(av.y);
            pa[(2 ^ ssw) << 3] = f2tf32(av.z);
            pa[(3 ^ ssw) << 3] = f2tf32(av.w);
            pb[(0 ^ ssw) << 3] = f2tf32(bv.x);
            pb[(1 ^ ssw) << 3] = f2tf32(bv.y);
            pb[(2 ^ ssw) << 3] = f2tf32(bv.z);
            pb[(3 ^ ssw) << 3] = f2tf32(bv.w);
        }
        __syncthreads();

        uint32_t a_all[4][8];
        #pragma unroll
        for (int r = 0; r < 4; r++) {
            const int m = wm + lq + r * 8;
            const uint32_t* p = &As[m * 36 + ((lc ^ ((m >> 3) & 3)) << 3)];
            *(uint4*)&a_all[r][0] = *(const uint4*)p;
            *(uint4*)&a_all[r][4] = *(const uint4*)(p + 4);
        }

        #pragma unroll
        for (int g = 0; g < 4; g++) {
            uint32_t bb[2][8];
            #pragma unroll
            for (int j = 0; j < 2; j++) {
                const int n = wn + (g * 2 + j) * 8 + lq;
                const uint32_t* p = &Bs[n * 36 + ((lc ^ ((n >> 3) & 3)) << 3)];
                *(uint4*)&bb[j][0] = *(const uint4*)p;
                *(uint4*)&bb[j][4] = *(const uint4*)(p + 4);
            }
            // ks-outer, nt-inner: acc reuse distance = 4 MMAs
            #pragma unroll
            for (int ks = 0; ks < 4; ks++) {
                #pragma unroll
                for (int j = 0; j < 2; j++) {
                    const int nt = g * 2 + j;
                    uint32_t af0[4] = {a_all[0][2 * ks], a_all[1][2 * ks],
                                       a_all[0][2 * ks + 1], a_all[1][2 * ks + 1]};
                    uint32_t af1[4] = {a_all[2][2 * ks], a_all[3][2 * ks],
                                       a_all[2][2 * ks + 1], a_all[3][2 * ks + 1]};
                    uint32_t bf[2] = {bb[j][2 * ks], bb[j][2 * ks + 1]};
                    mma_tf32(acc[0][nt], af0, bf);
                    mma_tf32(acc[1][nt], af1, bf);
                }
            }
        }
        __syncthreads();
    }

    #pragma unroll
    for (int mt = 0; mt < 2; mt++) {
        const int r0 = bm + wm + mt * 16 + lq;
        #pragma unroll
        for (int nt = 0; nt < 8; nt++) {
            const int c0 = bn + wn + nt * 8 + 2 * lc;
            *(float2*)(C + (size_t)r0 * N + c0) =
                make_float2(acc[mt][nt][0], acc[mt][nt][1]);
            *(float2*)(C + (size_t)(r0 + 8) * N + c0) =
                make_float2(acc[mt][nt][2], acc[mt][nt][3]);
        }
    }
}

// ---------------------------------------------------------------------------
// Fused gate + value_embeds mix, RoPE + RMSNorm (in place on g_qkv).
// ---------------------------------------------------------------------------
__global__ __launch_bounds__(128) void rope_rms_gate(
    float* __restrict__ qkv, const float* __restrict__ x,
    const float* __restrict__ ve, const float* __restrict__ rc,
    const float* __restrict__ rs, const float* __restrict__ wg)
{
    const int row = blockIdx.x;
    const int t = row & (Tn - 1);
    const int warp = threadIdx.x >> 5;
    const int lane = threadIdx.x & 31;

    for (int head = warp; head < HQn + 2 * HKn; head += 4) {
        float* p = qkv + (size_t)row * Fn + head * Dn;
        if (head < HQn + HKn) {
            float x1 = p[lane], x2 = p[lane + 32];
            float c = rc[t * (Dn / 2) + lane];
            float s = rs[t * (Dn / 2) + lane];
            float y1 = x1 * c - x2 * s;
            float y2 = x1 * s + x2 * c;
            float ss = y1 * y1 + y2 * y2;
            #pragma unroll
            for (int o = 16; o; o >>= 1) ss += __shfl_xor_sync(0xffffffffu, ss, o);
            float r = rsqrtf(ss * (1.0f / Dn) + 1e-8f);
            p[lane] = y1 * r;
            p[lane + 32] = y2 * r;
        } else {
            int hv = head - HQn - HKn;
            float pr = (lane < GATE_CHn)
                         ? x[(size_t)row * En + lane] * wg[hv * GATE_CHn + lane]
                         : 0.f;
            #pragma unroll
            for (int o = 16; o; o >>= 1) pr += __shfl_xor_sync(0xffffffffu, pr, o);
            float gate = 3.0f / (1.0f + __expf(-pr));
            const float* vp = ve + (size_t)row * (HKn * Dn) + hv * Dn;
            p[lane]      += gate * vp[lane];
            p[lane + 32] += gate * vp[lane + 32];
        }
    }
}

// ---------------------------------------------------------------------------
// Tensor-core flash attention v4: same layouts as v3, S computed with 4
// independent accumulator chains (hi/lo x k-parity) to hide MMA latency.
// ---------------------------------------------------------------------------
#define QTILE 128
#define KTILE 64

#define W_KHI 0
#define W_KLO (W_KHI + 64 * 68)
#define W_VS  (W_KLO + 64 * 68)
#define W_PS  (W_VS + 64 * 72)
#define ATTN_WORDS (W_PS + QTILE * 68)
#define ATTN_SMEM_BYTES (ATTN_WORDS * 4)

__global__ __launch_bounds__(256, 2) void attn_tc(
    const float* __restrict__ qkv, float* __restrict__ out)
{
    extern __shared__ uint32_t sm[];
    uint32_t* Khi = sm + W_KHI;
    uint32_t* Klo = sm + W_KLO;
    uint32_t* Vs  = sm + W_VS;
    uint32_t* Ps  = sm + W_PS;

    const int tid = threadIdx.x;
    const int lane = tid & 31;
    const int warp = tid >> 5;
    const int q0 = blockIdx.x * QTILE;
    const int h  = blockIdx.y;
    const int bb = blockIdx.z;
    const int hk = h >> 2;
    const int qoff = h * Dn;
    const int koff = (HQn + hk) * Dn;
    const int voff = (HQn + HKn + hk) * Dn;
    const int row0 = bb * Tn + q0;

    const int lq = lane >> 2;
    const int lc = lane & 3;
    const int rA = warp * 16 + lq;

    uint32_t qA[16], qB[16];
    {
        const float* q0p = qkv + (size_t)(row0 + rA) * Fn + qoff + lc;
        const float* q1p = qkv + (size_t)(row0 + rA + 8) * Fn + qoff + lc;
        #pragma unroll
        for (int j = 0; j < 16; j++) {
            qA[j] = f2tf32(q0p[4 * j] * 0.125f);
            qB[j] = f2tf32(q1p[4 * j] * 0.125f);
        }
    }

    float o[8][4];
    #pragma unroll
    for (int nt = 0; nt < 8; nt++)
        #pragma unroll
        for (int e = 0; e < 4; e++) o[nt][e] = 0.f;
    float lA = 0.f, lB = 0.f;

    const int kt_lo = (q0 > WINDOWn) ? ((q0 - WINDOWn) >> 6) : 0;
    const int kt_hi = (q0 + QTILE - 1) >> 6;

    for (int kt = kt_lo; kt <= kt_hi; kt++) {
        const int k0 = kt * KTILE;
        const int krow0 = bb * Tn + k0;
        __syncthreads();

        #pragma unroll
        for (int it = 0; it < 4; it++) {
            const int f = tid + 256 * it;
            const int r = f >> 4;
            const int c = (f & 15) * 4;
            float4 kv = *(const float4*)(qkv + (size_t)(krow0 + r) * Fn + koff + c);
            float4 vv = *(const float4*)(qkv + (size_t)(krow0 + r) * Fn + voff + c);
            const int sw = (r >> 3) & 3;
            uint32_t* ph = &Khi[r * 68 + (c >> 2)];
            uint32_t* pl = &Klo[r * 68 + (c >> 2)];
            float kk[4] = {kv.x, kv.y, kv.z, kv.w};
            #pragma unroll
            for (int i = 0; i < 4; i++) {
                uint32_t hi = f2tf32(kk[i]);
                ph[(i ^ sw) << 4] = hi;
                pl[(i ^ sw) << 4] = f2tf32(kk[i] - __uint_as_float(hi));
            }
            Vs[r * 72 + c + 0] = f2tf32(vv.x);
            Vs[r * 72 + c + 1] = f2tf32(vv.y);
            Vs[r * 72 + c + 2] = f2tf32(vv.z);
            Vs[r * 72 + c + 3] = f2tf32(vv.w);
        }
        __syncthreads();

        #pragma unroll
        for (int nt = 0; nt < 8; nt++) {
            const int key = nt * 8 + lq;
            const uint32_t* pk = &Khi[key * 68 + ((lc ^ ((key >> 3) & 3)) << 4)];
            const uint32_t* pl = &Klo[key * 68 + ((lc ^ ((key >> 3) & 3)) << 4)];
            uint32_t kh[16], kl[16];
            *(uint4*)&kh[0]  = *(const uint4*)(pk + 0);
            *(uint4*)&kh[4]  = *(const uint4*)(pk + 4);
            *(uint4*)&kh[8]  = *(const uint4*)(pk + 8);
            *(uint4*)&kh[12] = *(const uint4*)(pk + 12);
            *(uint4*)&kl[0]  = *(const uint4*)(pl + 0);
            *(uint4*)&kl[4]  = *(const uint4*)(pl + 4);
            *(uint4*)&kl[8]  = *(const uint4*)(pl + 8);
            *(uint4*)&kl[12] = *(const uint4*)(pl + 12);

            // 4 independent accumulator chains (hi/lo x ks-parity)
            float s0[4] = {0.f, 0.f, 0.f, 0.f};
            float s1[4] = {0.f, 0.f, 0.f, 0.f};
            float s2[4] = {0.f, 0.f, 0.f, 0.f};
            float s3[4] = {0.f, 0.f, 0.f, 0.f};
            #pragma unroll
            for (int kp = 0; kp < 4; kp++) {
                const int ka = 2 * kp, kbq = 2 * kp + 1;
                uint32_t afa[4] = {qA[2 * ka], qB[2 * ka],
                                   qA[2 * ka + 1], qB[2 * ka + 1]};
                uint32_t afb[4] = {qA[2 * kbq], qB[2 * kbq],
                                   qA[2 * kbq + 1], qB[2 * kbq + 1]};
                uint32_t bha[2] = {kh[2 * ka], kh[2 * ka + 1]};
                uint32_t bla[2] = {kl[2 * ka], kl[2 * ka + 1]};
                uint32_t bhb[2] = {kh[2 * kbq], kh[2 * kbq + 1]};
                uint32_t blb[2] = {kl[2 * kbq], kl[2 * kbq + 1]};
                mma_tf32(s0, afa, bha);
                mma_tf32(s1, afa, bla);
                mma_tf32(s2, afb, bhb);
                mma_tf32(s3, afb, blb);
            }

            float p[4];
            #pragma unroll
            for (int e = 0; e < 4; e++) {
                const float sv = (s0[e] + s1[e]) + (s2[e] + s3[e]);
                const int i = q0 + rA + ((e >= 2) ? 8 : 0);
                const int j = k0 + nt * 8 + 2 * lc + (e & 1);
                const bool live = (j <= i) && (j + WINDOWn >= i);
                p[e] = live ? __expf(sv - 8.0f) : 0.f;
            }
            lA += p[0] + p[1];
            lB += p[2] + p[3];

            #pragma unroll
            for (int e = 0; e < 4; e++) {
                const int col = nt * 8 + 2 * lc + (e & 1);
                const int pc = ((col & 3) << 4) | (col >> 2);
                const int row = rA + ((e >= 2) ? 8 : 0);
                Ps[row * 68 + (pc ^ (((row >> 3) & 3) << 4))] = f2tf32(p[e]);
            }
        }
        __syncwarp();

        uint32_t pA[16], pB[16];
        {
            const uint32_t* p0 = &Ps[rA * 68 + ((lc ^ ((rA >> 3) & 3)) << 4)];
            const int rB = rA + 8;
            const uint32_t* p1 = &Ps[rB * 68 + ((lc ^ ((rB >> 3) & 3)) << 4)];
            *(uint4*)&pA[0]  = *(const uint4*)(p0 + 0);
            *(uint4*)&pA[4]  = *(const uint4*)(p0 + 4);
            *(uint4*)&pA[8]  = *(const uint4*)(p0 + 8);
            *(uint4*)&pA[12] = *(const uint4*)(p0 + 12);
            *(uint4*)&pB[0]  = *(const uint4*)(p1 + 0);
            *(uint4*)&pB[4]  = *(const uint4*)(p1 + 4);
            *(uint4*)&pB[8]  = *(const uint4*)(p1 + 8);
            *(uint4*)&pB[12] = *(const uint4*)(p1 + 12);
        }
        #pragma unroll
        for (int ks = 0; ks < 8; ks++) {
            const int kp = ks * 8 + lc;
            uint32_t af[4] = {pA[2 * ks], pB[2 * ks],
                              pA[2 * ks + 1], pB[2 * ks + 1]};
            #pragma unroll
            for (int nt = 0; nt < 8; nt++) {
                const int d = nt * 8 + lq;
                uint32_t bf[2] = {Vs[kp * 72 + d], Vs[(kp + 4) * 72 + d]};
                mma_tf32(o[nt], af, bf);
            }
        }
    }

    lA += __shfl_xor_sync(0xffffffffu, lA, 1);
    lA += __shfl_xor_sync(0xffffffffu, lA, 2);
    lB += __shfl_xor_sync(0xffffffffu, lB, 1);
    lB += __shfl_xor_sync(0xffffffffu, lB, 2);
    const float invA = 1.0f / lA;
    const float invB = 1.0f / lB;

    #pragma unroll
    for (int nt = 0; nt < 8; nt++) {
        const int c0 = qoff + nt * 8 + 2 * lc;
        *(float2*)(out + (size_t)(row0 + rA) * En + c0) =
            make_float2(o[nt][0] * invA, o[nt][1] * invA);
        *(float2*)(out + (size_t)(row0 + rA + 8) * En + c0) =
            make_float2(o[nt][2] * invB, o[nt][3] * invB);
    }
}

// ---------------------------------------------------------------------------
extern "C" void kernel_launch(void* const* d_in, const int* in_sizes, int n_in,
                              void* d_out, int out_size)
{
    (void)in_sizes; (void)n_in; (void)out_size;
    const float* x    = (const float*)d_in[0];
    const float* ve   = (const float*)d_in[1];
    const float* rc   = (const float*)d_in[2];
    const float* rs   = (const float*)d_in[3];
    const float* wqkv = (const float*)d_in[4];
    const float* wg   = (const float*)d_in[5];
    const float* wo   = (const float*)d_in[6];
    float* out = (float*)d_out;

    float *qkv_p = nullptr, *att_p = nullptr;
    cudaGetSymbolAddress((void**)&qkv_p, g_qkv);
    cudaGetSymbolAddress((void**)&att_p, g_att);

    cudaFuncSetAttribute(attn_tc,
                         cudaFuncAttributeMaxDynamicSharedMemorySize,
                         ATTN_SMEM_BYTES);

    gemm_tf32<<<dim3(Fn / 128, Mn / 128), 256>>>(x, wqkv, qkv_p, Mn, Fn, En);
    rope_rms_gate<<<Mn, 128>>>(qkv_p, x, ve, rc, rs, wg);
    attn_tc<<<dim3(Tn / QTILE, HQn, Bn), 256, ATTN_SMEM_BYTES>>>(qkv_p, att_p);
    gemm_tf32<<<dim3(En / 128, Mn / 128), 256>>>(att_p, wo, out, Mn, En, En);
}

// round 7
// speedup vs baseline: 1.8320x; 1.4540x over previous
#include <cuda_runtime.h>
#include <math.h>
#include <stdint.h>

#define HQn 16
#define HKn 4
#define Dn 64
#define GATE_CHn 12
#define WINDOWn 1024
#define Bn 2
#define Tn 2048
#define En 1024
#define Fn 1536
#define Mn 4096

// Scratch (allocation-free rule: device globals)
__device__ __align__(256) float g_qkv[(size_t)Mn * Fn];
__device__ __align__(256) float g_att[(size_t)Mn * En];

// ---------------------------------------------------------------------------
// helpers
// ---------------------------------------------------------------------------
__device__ __forceinline__ uint32_t f2tf32(float x) {
    uint32_t r;
    asm("cvt.rna.tf32.f32 %0, %1;" : "=r"(r) : "f"(x));
    return r;
}

__device__ __forceinline__ void mma_tf32(float* d, const uint32_t* a,
                                         const uint32_t* b) {
    asm volatile(
        "mma.sync.aligned.m16n8k8.row.col.f32.tf32.tf32.f32 "
        "{%0,%1,%2,%3}, {%4,%5,%6,%7}, {%8,%9}, {%0,%1,%2,%3};\n"
        : "+f"(d[0]), "+f"(d[1]), "+f"(d[2]), "+f"(d[3])
        : "r"(a[0]), "r"(a[1]), "r"(a[2]), "r"(a[3]), "r"(b[0]), "r"(b[1]));
}

__device__ __forceinline__ uint32_t sma(const void* p) {
    return (uint32_t)__cvta_generic_to_shared(p);
}
__device__ __forceinline__ void cp16(uint32_t dst, const void* src) {
    asm volatile("cp.async.cg.shared.global [%0], [%1], 16;\n"
                 :: "r"(dst), "l"(src));
}
__device__ __forceinline__ void cp_commit() {
    asm volatile("cp.async.commit_group;\n");
}
template <int N>
__device__ __forceinline__ void cp_wait() {
    asm volatile("cp.async.wait_group %0;\n" :: "n"(N));
}

// ---------------------------------------------------------------------------
// TF32 GEMM: C[M,N] = A[M,K] * B[N,K]^T. cp.async double-buffered, raw fp32
// smem (stride 36 words/row, no swizzle: both cp.async stores and scalar
// fragment loads are bank-conflict-free), cvt to tf32 at fragment load.
// 128x128 tile, BK=32, 8 warps (warp: 32m x 64n).
// ---------------------------------------------------------------------------
#define GBUF_W (128 * 36)          // words per operand tile
#define GEMM_SMEM_BYTES (4 * GBUF_W * 4)   // 2 bufs x (A+B)

__global__ __launch_bounds__(256, 2) void gemm_tf32(
    const float* __restrict__ A, const float* __restrict__ Bm,
    float* __restrict__ C, int M, int N, int K)
{
    extern __shared__ float dynsm[];

    const int tid = threadIdx.x;
    const int lane = tid & 31;
    const int warp = tid >> 5;
    const int wm = (warp & 3) * 32;
    const int wn = (warp >> 2) * 64;
    const int bm = blockIdx.y * 128;
    const int bn = blockIdx.x * 128;
    const int lq = lane >> 2;
    const int lc = lane & 3;

    float acc[2][8][4];
    #pragma unroll
    for (int mt = 0; mt < 2; mt++)
        #pragma unroll
        for (int nt = 0; nt < 8; nt++)
            #pragma unroll
            for (int i = 0; i < 4; i++) acc[mt][nt][i] = 0.f;

    // prefetch one 128x32 A tile + 128x32 B tile into buffer b
    auto pref = [&](int b, int k0) {
        float* Ad = dynsm + b * (2 * GBUF_W);
        float* Bd = Ad + GBUF_W;
        #pragma unroll
        for (int i = 0; i < 4; i++) {
            const int g = tid + 256 * i;
            const int row = g >> 3;
            const int c4 = (g & 7) * 4;
            cp16(sma(Ad + row * 36 + c4), A + (size_t)(bm + row) * K + k0 + c4);
            cp16(sma(Bd + row * 36 + c4), Bm + (size_t)(bn + row) * K + k0 + c4);
        }
    };

    const int niter = K / 32;
    pref(0, 0);
    cp_commit();

    for (int ki = 0; ki < niter; ki++) {
        if (ki + 1 < niter) {
            pref((ki + 1) & 1, (ki + 1) * 32);
            cp_commit();
            cp_wait<1>();
        } else {
            cp_wait<0>();
        }
        __syncthreads();

        const float* Ac = dynsm + (ki & 1) * (2 * GBUF_W);
        const float* Bc = Ac + GBUF_W;

        // A fragments: rows wm+lq+8r, k = lc+4j (scalar, conflict-free), cvt
        uint32_t a_all[4][8];
        #pragma unroll
        for (int r = 0; r < 4; r++) {
            const float* p = Ac + (wm + lq + 8 * r) * 36 + lc;
            #pragma unroll
            for (int j = 0; j < 8; j++)
                a_all[r][j] = f2tf32(p[4 * j]);
        }

        #pragma unroll
        for (int nt = 0; nt < 8; nt++) {
            const float* p = Bc + (wn + nt * 8 + lq) * 36 + lc;
            uint32_t bbv[8];
            #pragma unroll
            for (int j = 0; j < 8; j++)
                bbv[j] = f2tf32(p[4 * j]);
            #pragma unroll
            for (int ks = 0; ks < 4; ks++) {
                uint32_t af0[4] = {a_all[0][2 * ks], a_all[1][2 * ks],
                                   a_all[0][2 * ks + 1], a_all[1][2 * ks + 1]};
                uint32_t af1[4] = {a_all[2][2 * ks], a_all[3][2 * ks],
                                   a_all[2][2 * ks + 1], a_all[3][2 * ks + 1]};
                uint32_t bf[2] = {bbv[2 * ks], bbv[2 * ks + 1]};
                mma_tf32(acc[0][nt], af0, bf);
                mma_tf32(acc[1][nt], af1, bf);
            }
        }
        __syncthreads();
    }

    #pragma unroll
    for (int mt = 0; mt < 2; mt++) {
        const int r0 = bm + wm + mt * 16 + lq;
        #pragma unroll
        for (int nt = 0; nt < 8; nt++) {
            const int c0 = bn + wn + nt * 8 + 2 * lc;
            *(float2*)(C + (size_t)r0 * N + c0) =
                make_float2(acc[mt][nt][0], acc[mt][nt][1]);
            *(float2*)(C + (size_t)(r0 + 8) * N + c0) =
                make_float2(acc[mt][nt][2], acc[mt][nt][3]);
        }
    }
}

// ---------------------------------------------------------------------------
// Fused gate + value_embeds mix, RoPE + RMSNorm (in place on g_qkv).
// ---------------------------------------------------------------------------
__global__ __launch_bounds__(128) void rope_rms_gate(
    float* __restrict__ qkv, const float* __restrict__ x,
    const float* __restrict__ ve, const float* __restrict__ rc,
    const float* __restrict__ rs, const float* __restrict__ wg)
{
    const int row = blockIdx.x;
    const int t = row & (Tn - 1);
    const int warp = threadIdx.x >> 5;
    const int lane = threadIdx.x & 31;

    for (int head = warp; head < HQn + 2 * HKn; head += 4) {
        float* p = qkv + (size_t)row * Fn + head * Dn;
        if (head < HQn + HKn) {
            float x1 = p[lane], x2 = p[lane + 32];
            float c = rc[t * (Dn / 2) + lane];
            float s = rs[t * (Dn / 2) + lane];
            float y1 = x1 * c - x2 * s;
            float y2 = x1 * s + x2 * c;
            float ss = y1 * y1 + y2 * y2;
            #pragma unroll
            for (int o = 16; o; o >>= 1) ss += __shfl_xor_sync(0xffffffffu, ss, o);
            float r = rsqrtf(ss * (1.0f / Dn) + 1e-8f);
            p[lane] = y1 * r;
            p[lane + 32] = y2 * r;
        } else {
            int hv = head - HQn - HKn;
            float pr = (lane < GATE_CHn)
                         ? x[(size_t)row * En + lane] * wg[hv * GATE_CHn + lane]
                         : 0.f;
            #pragma unroll
            for (int o = 16; o; o >>= 1) pr += __shfl_xor_sync(0xffffffffu, pr, o);
            float gate = 3.0f / (1.0f + __expf(-pr));
            const float* vp = ve + (size_t)row * (HKn * Dn) + hv * Dn;
            p[lane]      += gate * vp[lane];
            p[lane + 32] += gate * vp[lane + 32];
        }
    }
}

// ---------------------------------------------------------------------------
// Tensor-core flash attention v5: cp.async double-buffered raw K/V tiles,
// hi/lo K split + tf32 cvt at fragment-load time, register Q fragments,
// fixed-max softmax. K stride 68, V stride 72 (conflict-free stores/loads),
// Ps keeps the v4 permuted-swizzled tf32 layout.
// ---------------------------------------------------------------------------
#define QTILE 128
#define KTILE 64
#define KV_K_W (64 * 68)
#define KV_V_W (64 * 72)
#define KV_BUF_W (KV_K_W + KV_V_W)
#define W_PS (2 * KV_BUF_W)
#define ATTN_WORDS (W_PS + QTILE * 68)
#define ATTN_SMEM_BYTES (ATTN_WORDS * 4)

__global__ __launch_bounds__(256, 2) void attn_tc(
    const float* __restrict__ qkv, float* __restrict__ out)
{
    extern __shared__ float asm_f[];
    uint32_t* Ps = (uint32_t*)(asm_f + W_PS);

    const int tid = threadIdx.x;
    const int lane = tid & 31;
    const int warp = tid >> 5;
    const int q0 = blockIdx.x * QTILE;
    const int h  = blockIdx.y;
    const int bb = blockIdx.z;
    const int hk = h >> 2;
    const int qoff = h * Dn;
    const int koff = (HQn + hk) * Dn;
    const int voff = (HQn + HKn + hk) * Dn;
    const int row0 = bb * Tn + q0;

    const int lq = lane >> 2;
    const int lc = lane & 3;
    const int rA = warp * 16 + lq;

    // Q fragments in registers (once), scaled by 1/8
    uint32_t qA[16], qB[16];
    {
        const float* q0p = qkv + (size_t)(row0 + rA) * Fn + qoff + lc;
        const float* q1p = qkv + (size_t)(row0 + rA + 8) * Fn + qoff + lc;
        #pragma unroll
        for (int j = 0; j < 16; j++) {
            qA[j] = f2tf32(q0p[4 * j] * 0.125f);
            qB[j] = f2tf32(q1p[4 * j] * 0.125f);
        }
    }

    float o[8][4];
    #pragma unroll
    for (int nt = 0; nt < 8; nt++)
        #pragma unroll
        for (int e = 0; e < 4; e++) o[nt][e] = 0.f;
    float lA = 0.f, lB = 0.f;

    const int kt_lo = (q0 > WINDOWn) ? ((q0 - WINDOWn) >> 6) : 0;
    const int kt_hi = (q0 + QTILE - 1) >> 6;

    auto pref = [&](int b, int kt) {
        const int krow0 = bb * Tn + kt * KTILE;
        float* Kd = asm_f + b * KV_BUF_W;
        float* Vd = Kd + KV_K_W;
        #pragma unroll
        for (int i = 0; i < 4; i++) {
            const int g = tid + 256 * i;
            const int row = g >> 4;
            const int c4 = (g & 15) * 4;
            const float* src = qkv + (size_t)(krow0 + row) * Fn;
            cp16(sma(Kd + row * 68 + c4), src + koff + c4);
            cp16(sma(Vd + row * 72 + c4), src + voff + c4);
        }
    };

    pref(0, kt_lo);
    cp_commit();

    for (int kt = kt_lo; kt <= kt_hi; kt++) {
        const int cur = (kt - kt_lo) & 1;
        if (kt < kt_hi) {
            pref(cur ^ 1, kt + 1);
            cp_commit();
            cp_wait<1>();
        } else {
            cp_wait<0>();
        }
        __syncthreads();

        const float* Kc = asm_f + cur * KV_BUF_W;
        const float* Vc = Kc + KV_K_W;
        const int k0 = kt * KTILE;

        // ---- S = Q K^T with K hi/lo split computed at load
        #pragma unroll
        for (int nt = 0; nt < 8; nt++) {
            const int key = nt * 8 + lq;
            const float* kp_base = Kc + key * 68 + lc;

            float s0[4] = {0.f, 0.f, 0.f, 0.f};
            float s1[4] = {0.f, 0.f, 0.f, 0.f};
            float s2[4] = {0.f, 0.f, 0.f, 0.f};
            float s3[4] = {0.f, 0.f, 0.f, 0.f};

            #pragma unroll
            for (int half = 0; half < 2; half++) {
                uint32_t kh[8], kl[8];
                #pragma unroll
                for (int j = 0; j < 8; j++) {
                    const float kraw = kp_base[4 * (half * 8 + j)];
                    const uint32_t hi = f2tf32(kraw);
                    kh[j] = hi;
                    kl[j] = f2tf32(kraw - __uint_as_float(hi));
                }
                #pragma unroll
                for (int kp2 = 0; kp2 < 2; kp2++) {
                    const int jg = half * 8 + 4 * kp2;   // q index base
                    const int jl = 4 * kp2;              // local kh/kl base
                    uint32_t afa[4] = {qA[jg], qB[jg], qA[jg + 1], qB[jg + 1]};
                    uint32_t afb[4] = {qA[jg + 2], qB[jg + 2],
                                       qA[jg + 3], qB[jg + 3]};
                    uint32_t bha[2] = {kh[jl], kh[jl + 1]};
                    uint32_t bla[2] = {kl[jl], kl[jl + 1]};
                    uint32_t bhb[2] = {kh[jl + 2], kh[jl + 3]};
                    uint32_t blb[2] = {kl[jl + 2], kl[jl + 3]};
                    mma_tf32(s0, afa, bha);
                    mma_tf32(s1, afa, bla);
                    mma_tf32(s2, afb, bhb);
                    mma_tf32(s3, afb, blb);
                }
            }

            // mask + fixed-max softmax (rms-norm => |s| <= 8)
            float p[4];
            #pragma unroll
            for (int e = 0; e < 4; e++) {
                const float sv = (s0[e] + s1[e]) + (s2[e] + s3[e]);
                const int i = q0 + rA + ((e >= 2) ? 8 : 0);
                const int j = k0 + nt * 8 + 2 * lc + (e & 1);
                const bool live = (j <= i) && (j + WINDOWn >= i);
                p[e] = live ? __expf(sv - 8.0f) : 0.f;
            }
            lA += p[0] + p[1];
            lB += p[2] + p[3];

            #pragma unroll
            for (int e = 0; e < 4; e++) {
                const int col = nt * 8 + 2 * lc + (e & 1);
                const int pc = ((col & 3) << 4) | (col >> 2);
                const int row = rA + ((e >= 2) ? 8 : 0);
                Ps[row * 68 + (pc ^ (((row >> 3) & 3) << 4))] = f2tf32(p[e]);
            }
        }
        __syncwarp();   // own-warp P rows only

        // ---- O += P V
        uint32_t pA[16], pB[16];
        {
            const uint32_t* p0 = &Ps[rA * 68 + ((lc ^ ((rA >> 3) & 3)) << 4)];
            const int rB = rA + 8;
            const uint32_t* p1 = &Ps[rB * 68 + ((lc ^ ((rB >> 3) & 3)) << 4)];
            *(uint4*)&pA[0]  = *(const uint4*)(p0 + 0);
            *(uint4*)&pA[4]  = *(const uint4*)(p0 + 4);
            *(uint4*)&pA[8]  = *(const uint4*)(p0 + 8);
            *(uint4*)&pA[12] = *(const uint4*)(p0 + 12);
            *(uint4*)&pB[0]  = *(const uint4*)(p1 + 0);
            *(uint4*)&pB[4]  = *(const uint4*)(p1 + 4);
            *(uint4*)&pB[8]  = *(const uint4*)(p1 + 8);
            *(uint4*)&pB[12] = *(const uint4*)(p1 + 12);
        }
        #pragma unroll
        for (int ks = 0; ks < 8; ks++) {
            const int kp = ks * 8 + lc;
            uint32_t af[4] = {pA[2 * ks], pB[2 * ks],
                              pA[2 * ks + 1], pB[2 * ks + 1]};
            #pragma unroll
            for (int nt = 0; nt < 8; nt++) {
                const int d = nt * 8 + lq;
                uint32_t bf[2] = {f2tf32(Vc[kp * 72 + d]),
                                  f2tf32(Vc[(kp + 4) * 72 + d])};
                mma_tf32(o[nt], af, bf);
            }
        }
        __syncthreads();   // done reading cur before next prefetch overwrites
    }

    lA += __shfl_xor_sync(0xffffffffu, lA, 1);
    lA += __shfl_xor_sync(0xffffffffu, lA, 2);
    lB += __shfl_xor_sync(0xffffffffu, lB, 1);
    lB += __shfl_xor_sync(0xffffffffu, lB, 2);
    const float invA = 1.0f / lA;
    const float invB = 1.0f / lB;

    #pragma unroll
    for (int nt = 0; nt < 8; nt++) {
        const int c0 = qoff + nt * 8 + 2 * lc;
        *(float2*)(out + (size_t)(row0 + rA) * En + c0) =
            make_float2(o[nt][0] * invA, o[nt][1] * invA);
        *(float2*)(out + (size_t)(row0 + rA + 8) * En + c0) =
            make_float2(o[nt][2] * invB, o[nt][3] * invB);
    }
}

// ---------------------------------------------------------------------------
extern "C" void kernel_launch(void* const* d_in, const int* in_sizes, int n_in,
                              void* d_out, int out_size)
{
    (void)in_sizes; (void)n_in; (void)out_size;
    const float* x    = (const float*)d_in[0];
    const float* ve   = (const float*)d_in[1];
    const float* rc   = (const float*)d_in[2];
    const float* rs   = (const float*)d_in[3];
    const float* wqkv = (const float*)d_in[4];
    const float* wg   = (const float*)d_in[5];
    const float* wo   = (const float*)d_in[6];
    float* out = (float*)d_out;

    float *qkv_p = nullptr, *att_p = nullptr;
    cudaGetSymbolAddress((void**)&qkv_p, g_qkv);
    cudaGetSymbolAddress((void**)&att_p, g_att);

    cudaFuncSetAttribute(gemm_tf32,
                         cudaFuncAttributeMaxDynamicSharedMemorySize,
                         GEMM_SMEM_BYTES);
    cudaFuncSetAttribute(attn_tc,
                         cudaFuncAttributeMaxDynamicSharedMemorySize,
                         ATTN_SMEM_BYTES);

    gemm_tf32<<<dim3(Fn / 128, Mn / 128), 256, GEMM_SMEM_BYTES>>>(
        x, wqkv, qkv_p, Mn, Fn, En);
    rope_rms_gate<<<Mn, 128>>>(qkv_p, x, ve, rc, rs, wg);
    attn_tc<<<dim3(Tn / QTILE, HQn, Bn), 256, ATTN_SMEM_BYTES>>>(qkv_p, att_p);
    gemm_tf32<<<dim3(En / 128, Mn / 128), 256, GEMM_SMEM_BYTES>>>(
        att_p, wo, out, Mn, En, En);
}

// round 8
// speedup vs baseline: 1.9511x; 1.0650x over previous
#include <cuda_runtime.h>
#include <math.h>
#include <stdint.h>

#define HQn 16
#define HKn 4
#define Dn 64
#define GATE_CHn 12
#define WINDOWn 1024
#define Bn 2
#define Tn 2048
#define En 1024
#define Fn 1536
#define Mn 4096

// Scratch (allocation-free rule: device globals)
__device__ __align__(256) float g_qkv[(size_t)Mn * Fn];
__device__ __align__(256) float g_att[(size_t)Mn * En];
// packed tf32 operands produced by rope_rms_pack
__device__ __align__(256) uint32_t g_qpack[(size_t)Bn * HQn * Tn * Dn];
__device__ __align__(256) uint32_t g_kpack[(size_t)Bn * HKn * Tn * 2 * Dn];
__device__ __align__(256) uint32_t g_vpack[(size_t)Bn * HKn * Tn * Dn];

// ---------------------------------------------------------------------------
// helpers
// ---------------------------------------------------------------------------
__device__ __forceinline__ uint32_t f2tf32(float x) {
    uint32_t r;
    asm("cvt.rna.tf32.f32 %0, %1;" : "=r"(r) : "f"(x));
    return r;
}

__device__ __forceinline__ void mma_tf32(float* d, const uint32_t* a,
                                         const uint32_t* b) {
    asm volatile(
        "mma.sync.aligned.m16n8k8.row.col.f32.tf32.tf32.f32 "
        "{%0,%1,%2,%3}, {%4,%5,%6,%7}, {%8,%9}, {%0,%1,%2,%3};\n"
        : "+f"(d[0]), "+f"(d[1]), "+f"(d[2]), "+f"(d[3])
        : "r"(a[0]), "r"(a[1]), "r"(a[2]), "r"(a[3]), "r"(b[0]), "r"(b[1]));
}

__device__ __forceinline__ uint32_t sma(const void* p) {
    return (uint32_t)__cvta_generic_to_shared(p);
}
__device__ __forceinline__ void cp16(uint32_t dst, const void* src) {
    asm volatile("cp.async.cg.shared.global [%0], [%1], 16;\n"
                 :: "r"(dst), "l"(src));
}
__device__ __forceinline__ void cp_commit() {
    asm volatile("cp.async.commit_group;\n");
}
template <int N>
__device__ __forceinline__ void cp_wait() {
    asm volatile("cp.async.wait_group %0;\n" :: "n"(N));
}

__device__ __forceinline__ int permd(int d) {     // k-run-contiguous permute
    return (d & 3) * 16 + (d >> 2);
}

// ---------------------------------------------------------------------------
// TF32 GEMM: C[M,N] = A[M,K] * B[N,K]^T. cp.async double-buffered, raw fp32
// smem (stride 36, conflict-free), cvt at fragment load. 128x128, BK=32.
// ---------------------------------------------------------------------------
#define GBUF_W (128 * 36)
#define GEMM_SMEM_BYTES (4 * GBUF_W * 4)

__global__ __launch_bounds__(256, 2) void gemm_tf32(
    const float* __restrict__ A, const float* __restrict__ Bm,
    float* __restrict__ C, int M, int N, int K)
{
    extern __shared__ float dynsm[];

    const int tid = threadIdx.x;
    const int lane = tid & 31;
    const int warp = tid >> 5;
    const int wm = (warp & 3) * 32;
    const int wn = (warp >> 2) * 64;
    const int bm = blockIdx.y * 128;
    const int bn = blockIdx.x * 128;
    const int lq = lane >> 2;
    const int lc = lane & 3;

    float acc[2][8][4];
    #pragma unroll
    for (int mt = 0; mt < 2; mt++)
        #pragma unroll
        for (int nt = 0; nt < 8; nt++)
            #pragma unroll
            for (int i = 0; i < 4; i++) acc[mt][nt][i] = 0.f;

    auto pref = [&](int b, int k0) {
        float* Ad = dynsm + b * (2 * GBUF_W);
        float* Bd = Ad + GBUF_W;
        #pragma unroll
        for (int i = 0; i < 4; i++) {
            const int g = tid + 256 * i;
            const int row = g >> 3;
            const int c4 = (g & 7) * 4;
            cp16(sma(Ad + row * 36 + c4), A + (size_t)(bm + row) * K + k0 + c4);
            cp16(sma(Bd + row * 36 + c4), Bm + (size_t)(bn + row) * K + k0 + c4);
        }
    };

    const int niter = K / 32;
    pref(0, 0);
    cp_commit();

    for (int ki = 0; ki < niter; ki++) {
        if (ki + 1 < niter) {
            pref((ki + 1) & 1, (ki + 1) * 32);
            cp_commit();
            cp_wait<1>();
        } else {
            cp_wait<0>();
        }
        __syncthreads();

        const float* Ac = dynsm + (ki & 1) * (2 * GBUF_W);
        const float* Bc = Ac + GBUF_W;

        uint32_t a_all[4][8];
        #pragma unroll
        for (int r = 0; r < 4; r++) {
            const float* p = Ac + (wm + lq + 8 * r) * 36 + lc;
            #pragma unroll
            for (int j = 0; j < 8; j++)
                a_all[r][j] = f2tf32(p[4 * j]);
        }

        #pragma unroll
        for (int nt = 0; nt < 8; nt++) {
            const float* p = Bc + (wn + nt * 8 + lq) * 36 + lc;
            uint32_t bbv[8];
            #pragma unroll
            for (int j = 0; j < 8; j++)
                bbv[j] = f2tf32(p[4 * j]);
            #pragma unroll
            for (int ks = 0; ks < 4; ks++) {
                uint32_t af0[4] = {a_all[0][2 * ks], a_all[1][2 * ks],
                                   a_all[0][2 * ks + 1], a_all[1][2 * ks + 1]};
                uint32_t af1[4] = {a_all[2][2 * ks], a_all[3][2 * ks],
                                   a_all[2][2 * ks + 1], a_all[3][2 * ks + 1]};
                uint32_t bf[2] = {bbv[2 * ks], bbv[2 * ks + 1]};
                mma_tf32(acc[0][nt], af0, bf);
                mma_tf32(acc[1][nt], af1, bf);
            }
        }
        __syncthreads();
    }

    #pragma unroll
    for (int mt = 0; mt < 2; mt++) {
        const int r0 = bm + wm + mt * 16 + lq;
        #pragma unroll
        for (int nt = 0; nt < 8; nt++) {
            const int c0 = bn + wn + nt * 8 + 2 * lc;
            *(float2*)(C + (size_t)r0 * N + c0) =
                make_float2(acc[mt][nt][0], acc[mt][nt][1]);
            *(float2*)(C + (size_t)(r0 + 8) * N + c0) =
                make_float2(acc[mt][nt][2], acc[mt][nt][3]);
        }
    }
}

// ---------------------------------------------------------------------------
// rope_rms_pack: gate + value_embeds mix, RoPE + RMSNorm, and PRE-CONVERT
// everything to packed tf32 operand buffers for the attention kernel:
//   qpack[b][h][t][permd(d)]        = tf32(q_hat[d] * 0.125)
//   kpack[b][hk][t][0..63 =permd]   = tf32(k_hat[d])         (hi)
//   kpack[b][hk][t][64+permd]       = tf32(k_hat[d] - hi)    (lo)
//   vpack[b][hk][t][d]              = tf32(v_mixed[d])       (plain order)
// ---------------------------------------------------------------------------
__global__ __launch_bounds__(128) void rope_rms_pack(
    const float* __restrict__ qkv, const float* __restrict__ x,
    const float* __restrict__ ve, const float* __restrict__ rc,
    const float* __restrict__ rs, const float* __restrict__ wg,
    uint32_t* __restrict__ qpack, uint32_t* __restrict__ kpack,
    uint32_t* __restrict__ vpack)
{
    const int row = blockIdx.x;            // b*Tn + t
    const int t = row & (Tn - 1);
    const int b = row >> 11;
    const int warp = threadIdx.x >> 5;
    const int lane = threadIdx.x & 31;

    for (int head = warp; head < HQn + 2 * HKn; head += 4) {
        const float* p = qkv + (size_t)row * Fn + head * Dn;
        if (head < HQn + HKn) {
            float x1 = p[lane], x2 = p[lane + 32];
            float c = rc[t * (Dn / 2) + lane];
            float s = rs[t * (Dn / 2) + lane];
            float y1 = x1 * c - x2 * s;
            float y2 = x1 * s + x2 * c;
            float ss = y1 * y1 + y2 * y2;
            #pragma unroll
            for (int o = 16; o; o >>= 1) ss += __shfl_xor_sync(0xffffffffu, ss, o);
            float r = rsqrtf(ss * (1.0f / Dn) + 1e-8f);
            y1 *= r; y2 *= r;
            if (head < HQn) {
                uint32_t* qp = qpack + ((size_t)(b * HQn + head) * Tn + t) * Dn;
                qp[permd(lane)]      = f2tf32(y1 * 0.125f);
                qp[permd(lane + 32)] = f2tf32(y2 * 0.125f);
            } else {
                const int hk = head - HQn;
                uint32_t* kp = kpack +
                    ((size_t)(b * HKn + hk) * Tn + t) * (2 * Dn);
                uint32_t h1 = f2tf32(y1);
                uint32_t h2 = f2tf32(y2);
                kp[permd(lane)]           = h1;
                kp[permd(lane + 32)]      = h2;
                kp[64 + permd(lane)]      = f2tf32(y1 - __uint_as_float(h1));
                kp[64 + permd(lane + 32)] = f2tf32(y2 - __uint_as_float(h2));
            }
        } else {
            const int hv = head - HQn - HKn;
            float pr = (lane < GATE_CHn)
                         ? x[(size_t)row * En + lane] * wg[hv * GATE_CHn + lane]
                         : 0.f;
            #pragma unroll
            for (int o = 16; o; o >>= 1) pr += __shfl_xor_sync(0xffffffffu, pr, o);
            float gate = 3.0f / (1.0f + __expf(-pr));
            const float* vp = ve + (size_t)row * (HKn * Dn) + hv * Dn;
            uint32_t* vd = vpack + ((size_t)(b * HKn + hv) * Tn + t) * Dn;
            vd[lane]      = f2tf32(p[lane]      + gate * vp[lane]);
            vd[lane + 32] = f2tf32(p[lane + 32] + gate * vp[lane + 32]);
        }
    }
}

// ---------------------------------------------------------------------------
// Tensor-core flash attention v6: pre-converted tf32 operands, zero cvt in
// the mainloop. KTILE=32, cp.async double-buffered khi/klo/v, K fragments
// via LDS.128 (permuted layout), register Q, fixed-max softmax, Ps swizzled.
// Smem: 2 x (khi 32x68 + klo 32x68 + v 32x72) + Ps 128x36 = 70 KB -> 2 CTA/SM.
// ---------------------------------------------------------------------------
#define QTILE 128
#define KTILE 32
#define AK_W (32 * 68)
#define AV_W (32 * 72)
#define ABUF_W (2 * AK_W + AV_W)
#define W_PS2 (2 * ABUF_W)
#define ATTN_WORDS (W_PS2 + QTILE * 36)
#define ATTN_SMEM_BYTES (ATTN_WORDS * 4)

__global__ __launch_bounds__(256, 2) void attn_tc(
    const uint32_t* __restrict__ qpack, const uint32_t* __restrict__ kpack,
    const uint32_t* __restrict__ vpack, float* __restrict__ out)
{
    extern __shared__ uint32_t smu[];
    uint32_t* Ps = smu + W_PS2;

    const int tid = threadIdx.x;
    const int lane = tid & 31;
    const int warp = tid >> 5;
    const int q0 = blockIdx.x * QTILE;
    const int h  = blockIdx.y;
    const int bb = blockIdx.z;
    const int hk = h >> 2;
    const int row0 = bb * Tn + q0;

    const int lq = lane >> 2;
    const int lc = lane & 3;
    const int rA = warp * 16 + lq;

    const uint32_t* kp_base = kpack + (size_t)(bb * HKn + hk) * Tn * (2 * Dn);
    const uint32_t* vp_base = vpack + (size_t)(bb * HKn + hk) * Tn * Dn;

    // ---- Q fragments (tf32, pre-scaled), LDG.128 x4 per row
    uint32_t qA[16], qB[16];
    {
        const uint32_t* qp0 = qpack +
            ((size_t)(bb * HQn + h) * Tn + q0 + rA) * Dn + lc * 16;
        const uint32_t* qp1 = qp0 + 8 * Dn;
        #pragma unroll
        for (int u = 0; u < 4; u++) {
            *(uint4*)&qA[4 * u] = *(const uint4*)(qp0 + 4 * u);
            *(uint4*)&qB[4 * u] = *(const uint4*)(qp1 + 4 * u);
        }
    }

    float o[8][4];
    #pragma unroll
    for (int nt = 0; nt < 8; nt++)
        #pragma unroll
        for (int e = 0; e < 4; e++) o[nt][e] = 0.f;
    float lA = 0.f, lB = 0.f;

    const int kt_lo = (q0 > WINDOWn) ? ((q0 - WINDOWn) >> 5) : 0;
    const int kt_hi = (q0 + QTILE - 1) >> 5;

    auto pref = [&](int bidx, int kt) {
        const int kbase = kt * KTILE;
        uint32_t* Kd = smu + bidx * ABUF_W;
        uint32_t* Ld = Kd + AK_W;
        uint32_t* Vd = Ld + AK_W;
        #pragma unroll
        for (int i = 0; i < 6; i++) {
            const int g = tid + 256 * i;
            const int reg = g >> 9;
            const int idx = g & 511;
            const int row = idx >> 4;
            const int c4 = (idx & 15) * 4;
            if (reg == 0)
                cp16(sma(Kd + row * 68 + c4),
                     kp_base + (size_t)(kbase + row) * 128 + c4);
            else if (reg == 1)
                cp16(sma(Ld + row * 68 + c4),
                     kp_base + (size_t)(kbase + row) * 128 + 64 + c4);
            else
                cp16(sma(Vd + row * 72 + c4),
                     vp_base + (size_t)(kbase + row) * 64 + c4);
        }
    };

    pref(0, kt_lo);
    cp_commit();

    for (int kt = kt_lo; kt <= kt_hi; kt++) {
        const int cur = (kt - kt_lo) & 1;
        if (kt < kt_hi) {
            pref(cur ^ 1, kt + 1);
            cp_commit();
            cp_wait<1>();
        } else {
            cp_wait<0>();
        }
        __syncthreads();

        const uint32_t* Khi = smu + cur * ABUF_W;
        const uint32_t* Klo = Khi + AK_W;
        const uint32_t* Vv  = Klo + AK_W;
        const int k0 = kt * KTILE;
        const int swP = (warp * 2) & 3;   // Ps swizzle (const per warp)

        // ---- S = Q K^T + softmax + P store, 4 groups of 8 keys
        #pragma unroll
        for (int nt = 0; nt < 4; nt++) {
            const int key = nt * 8 + lq;
            const uint32_t* ph = Khi + key * 68 + lc * 16;
            const uint32_t* pl = Klo + key * 68 + lc * 16;
            uint32_t kh[16], kl[16];
            #pragma unroll
            for (int u = 0; u < 4; u++) {
                *(uint4*)&kh[4 * u] = *(const uint4*)(ph + 4 * u);
                *(uint4*)&kl[4 * u] = *(const uint4*)(pl + 4 * u);
            }

            float s0[4] = {0.f, 0.f, 0.f, 0.f};
            float s1[4] = {0.f, 0.f, 0.f, 0.f};
            float s2[4] = {0.f, 0.f, 0.f, 0.f};
            float s3[4] = {0.f, 0.f, 0.f, 0.f};
            #pragma unroll
            for (int kp2 = 0; kp2 < 4; kp2++) {
                const int ka = 2 * kp2, kb = 2 * kp2 + 1;
                uint32_t afa[4] = {qA[2 * ka], qB[2 * ka],
                                   qA[2 * ka + 1], qB[2 * ka + 1]};
                uint32_t afb[4] = {qA[2 * kb], qB[2 * kb],
                                   qA[2 * kb + 1], qB[2 * kb + 1]};
                uint32_t bha[2] = {kh[2 * ka], kh[2 * ka + 1]};
                uint32_t bla[2] = {kl[2 * ka], kl[2 * ka + 1]};
                uint32_t bhb[2] = {kh[2 * kb], kh[2 * kb + 1]};
                uint32_t blb[2] = {kl[2 * kb], kl[2 * kb + 1]};
                mma_tf32(s0, afa, bha);
                mma_tf32(s1, afa, bla);
                mma_tf32(s2, afb, bhb);
                mma_tf32(s3, afb, blb);
            }

            float p[4];
            #pragma unroll
            for (int e = 0; e < 4; e++) {
                const float sv = (s0[e] + s1[e]) + (s2[e] + s3[e]);
                const int i = q0 + rA + ((e >= 2) ? 8 : 0);
                const int j = k0 + nt * 8 + 2 * lc + (e & 1);
                const bool live = (j <= i) && (j + WINDOWn >= i);
                p[e] = live ? __expf(sv - 8.0f) : 0.f;
            }
            lA += p[0] + p[1];
            lB += p[2] + p[3];

            #pragma unroll
            for (int e = 0; e < 4; e++) {
                const int col = nt * 8 + 2 * lc + (e & 1);
                const int row = rA + ((e >= 2) ? 8 : 0);
                Ps[row * 36 + (((col & 3) ^ swP) << 3) + (col >> 2)] =
                    f2tf32(p[e]);
            }
        }
        __syncwarp();   // own-warp P rows only

        // ---- O += P V
        uint32_t pA[8], pB[8];
        {
            const uint32_t* p0 = &Ps[rA * 36 + ((lc ^ swP) << 3)];
            const uint32_t* p1 = &Ps[(rA + 8) * 36 + ((lc ^ swP) << 3)];
            *(uint4*)&pA[0] = *(const uint4*)p0;
            *(uint4*)&pA[4] = *(const uint4*)(p0 + 4);
            *(uint4*)&pB[0] = *(const uint4*)p1;
            *(uint4*)&pB[4] = *(const uint4*)(p1 + 4);
        }
        #pragma unroll
        for (int ks = 0; ks < 4; ks++) {
            const int kp = ks * 8 + lc;
            uint32_t af[4] = {pA[2 * ks], pB[2 * ks],
                              pA[2 * ks + 1], pB[2 * ks + 1]};
            #pragma unroll
            for (int nt = 0; nt < 8; nt++) {
                const int d = nt * 8 + lq;
                uint32_t bf[2] = {Vv[kp * 72 + d], Vv[(kp + 4) * 72 + d]};
                mma_tf32(o[nt], af, bf);
            }
        }
        __syncthreads();   // cur fully consumed before next pref overwrites
    }

    lA += __shfl_xor_sync(0xffffffffu, lA, 1);
    lA += __shfl_xor_sync(0xffffffffu, lA, 2);
    lB += __shfl_xor_sync(0xffffffffu, lB, 1);
    lB += __shfl_xor_sync(0xffffffffu, lB, 2);
    const float invA = 1.0f / lA;
    const float invB = 1.0f / lB;

    #pragma unroll
    for (int nt = 0; nt < 8; nt++) {
        const int c0 = h * Dn + nt * 8 + 2 * lc;
        *(float2*)(out + (size_t)(row0 + rA) * En + c0) =
            make_float2(o[nt][0] * invA, o[nt][1] * invA);
        *(float2*)(out + (size_t)(row0 + rA + 8) * En + c0) =
            make_float2(o[nt][2] * invB, o[nt][3] * invB);
    }
}

// ---------------------------------------------------------------------------
extern "C" void kernel_launch(void* const* d_in, const int* in_sizes, int n_in,
                              void* d_out, int out_size)
{
    (void)in_sizes; (void)n_in; (void)out_size;
    const float* x    = (const float*)d_in[0];
    const float* ve   = (const float*)d_in[1];
    const float* rc   = (const float*)d_in[2];
    const float* rs   = (const float*)d_in[3];
    const float* wqkv = (const float*)d_in[4];
    const float* wg   = (const float*)d_in[5];
    const float* wo   = (const float*)d_in[6];
    float* out = (float*)d_out;

    float *qkv_p = nullptr, *att_p = nullptr;
    uint32_t *qp = nullptr, *kp = nullptr, *vp = nullptr;
    cudaGetSymbolAddress((void**)&qkv_p, g_qkv);
    cudaGetSymbolAddress((void**)&att_p, g_att);
    cudaGetSymbolAddress((void**)&qp, g_qpack);
    cudaGetSymbolAddress((void**)&kp, g_kpack);
    cudaGetSymbolAddress((void**)&vp, g_vpack);

    cudaFuncSetAttribute(gemm_tf32,
                         cudaFuncAttributeMaxDynamicSharedMemorySize,
                         GEMM_SMEM_BYTES);
    cudaFuncSetAttribute(attn_tc,
                         cudaFuncAttributeMaxDynamicSharedMemorySize,
                         ATTN_SMEM_BYTES);

    gemm_tf32<<<dim3(Fn / 128, Mn / 128), 256, GEMM_SMEM_BYTES>>>(
        x, wqkv, qkv_p, Mn, Fn, En);
    rope_rms_pack<<<Mn, 128>>>(qkv_p, x, ve, rc, rs, wg, qp, kp, vp);
    attn_tc<<<dim3(Tn / QTILE, HQn, Bn), 256, ATTN_SMEM_BYTES>>>(
        qp, kp, vp, att_p);
    gemm_tf32<<<dim3(En / 128, Mn / 128), 256, GEMM_SMEM_BYTES>>>(
        att_p, wo, out, Mn, En, En);
}

// round 9
// speedup vs baseline: 2.1922x; 1.1236x over previous
#include <cuda_runtime.h>
#include <math.h>
#include <stdint.h>

#define HQn 16
#define HKn 4
#define Dn 64
#define GATE_CHn 12
#define WINDOWn 1024
#define Bn 2
#define Tn 2048
#define En 1024
#define Fn 1536
#define Mn 4096

// Scratch (allocation-free rule: device globals)
__device__ __align__(256) float g_qkv[(size_t)Mn * Fn];
__device__ __align__(256) float g_att[(size_t)Mn * En];     // tf32 bit patterns, permuted
__device__ __align__(256) uint32_t g_xc[(size_t)Mn * En];   // x, tf32+perm
__device__ __align__(256) uint32_t g_wqc[(size_t)Fn * En];  // w_qkv, tf32+perm
__device__ __align__(256) uint32_t g_woc[(size_t)En * En];  // w_o, tf32+perm
__device__ __align__(256) uint32_t g_qpack[(size_t)Bn * HQn * Tn * Dn];
__device__ __align__(256) uint32_t g_kpack[(size_t)Bn * HKn * Tn * Dn];
__device__ __align__(256) uint32_t g_vpack[(size_t)Bn * HKn * Tn * Dn];

// ---------------------------------------------------------------------------
// helpers
// ---------------------------------------------------------------------------
__device__ __forceinline__ uint32_t f2tf32(float x) {
    uint32_t r;
    asm("cvt.rna.tf32.f32 %0, %1;" : "=r"(r) : "f"(x));
    return r;
}

__device__ __forceinline__ void mma_tf32(float* d, const uint32_t* a,
                                         const uint32_t* b) {
    asm volatile(
        "mma.sync.aligned.m16n8k8.row.col.f32.tf32.tf32.f32 "
        "{%0,%1,%2,%3}, {%4,%5,%6,%7}, {%8,%9}, {%0,%1,%2,%3};\n"
        : "+f"(d[0]), "+f"(d[1]), "+f"(d[2]), "+f"(d[3])
        : "r"(a[0]), "r"(a[1]), "r"(a[2]), "r"(a[3]), "r"(b[0]), "r"(b[1]));
}

__device__ __forceinline__ uint32_t sma(const void* p) {
    return (uint32_t)__cvta_generic_to_shared(p);
}
__device__ __forceinline__ void cp16(uint32_t dst, const void* src) {
    asm volatile("cp.async.cg.shared.global [%0], [%1], 16;\n"
                 :: "r"(dst), "l"(src));
}
__device__ __forceinline__ void cp_commit() {
    asm volatile("cp.async.commit_group;\n");
}
template <int N>
__device__ __forceinline__ void cp_wait() {
    asm volatile("cp.async.wait_group %0;\n" :: "n"(N));
}

__device__ __forceinline__ int permd(int d) {     // 64-chunk k-run permute
    return (d & 3) * 16 + (d >> 2);
}

// ---------------------------------------------------------------------------
// Prepass: convert fp32 matrix to tf32 bit patterns with per-32-column-chunk
// permutation perm32(k) = (k&3)*8 + (k>>2). Consecutive 4 inputs (4j+i)
// scatter to {j, 8+j, 16+j, 24+j}.
// ---------------------------------------------------------------------------
__global__ void cvt_perm(const float* __restrict__ src,
                         uint32_t* __restrict__ dst, int nwords)
{
    const int idx = (blockIdx.x * blockDim.x + threadIdx.x) * 4;
    if (idx < nwords) {
        float4 v = *(const float4*)(src + idx);
        const int base = idx & ~31;
        const int j = (idx >> 2) & 7;
        dst[base + j]      = f2tf32(v.x);
        dst[base + 8 + j]  = f2tf32(v.y);
        dst[base + 16 + j] = f2tf32(v.z);
        dst[base + 24 + j] = f2tf32(v.w);
    }
}

// ---------------------------------------------------------------------------
// TF32 GEMM on pre-converted+permuted operands: C[M,N] = A[M,K] * B[N,K]^T.
// cp.async double-buffered, zero cvt in loop, all fragment loads LDS.128.
// 128x128 tile, BK=32, 8 warps (warp: 32m x 64n).
// ---------------------------------------------------------------------------
#define GBUF_W (128 * 36)
#define GEMM_SMEM_BYTES (4 * GBUF_W * 4)

__global__ __launch_bounds__(256, 2) void gemm_tf32u(
    const uint32_t* __restrict__ A, const uint32_t* __restrict__ Bm,
    float* __restrict__ C, int M, int N, int K)
{
    extern __shared__ uint32_t dynsm[];

    const int tid = threadIdx.x;
    const int lane = tid & 31;
    const int warp = tid >> 5;
    const int wm = (warp & 3) * 32;
    const int wn = (warp >> 2) * 64;
    const int bm = blockIdx.y * 128;
    const int bn = blockIdx.x * 128;
    const int lq = lane >> 2;
    const int lc = lane & 3;

    float acc[2][8][4];
    #pragma unroll
    for (int mt = 0; mt < 2; mt++)
        #pragma unroll
        for (int nt = 0; nt < 8; nt++)
            #pragma unroll
            for (int i = 0; i < 4; i++) acc[mt][nt][i] = 0.f;

    auto pref = [&](int b, int k0) {
        uint32_t* Ad = dynsm + b * (2 * GBUF_W);
        uint32_t* Bd = Ad + GBUF_W;
        #pragma unroll
        for (int i = 0; i < 4; i++) {
            const int g = tid + 256 * i;
            const int row = g >> 3;
            const int c4 = (g & 7) * 4;
            cp16(sma(Ad + row * 36 + c4), A + (size_t)(bm + row) * K + k0 + c4);
            cp16(sma(Bd + row * 36 + c4), Bm + (size_t)(bn + row) * K + k0 + c4);
        }
    };

    const int niter = K / 32;
    pref(0, 0);
    cp_commit();

    for (int ki = 0; ki < niter; ki++) {
        if (ki + 1 < niter) {
            pref((ki + 1) & 1, (ki + 1) * 32);
            cp_commit();
            cp_wait<1>();
        } else {
            cp_wait<0>();
        }
        __syncthreads();

        const uint32_t* Ac = dynsm + (ki & 1) * (2 * GBUF_W);
        const uint32_t* Bc = Ac + GBUF_W;

        // a_all[r][j] = A[wm+lq+8r][k0 + lc + 4j]  (permuted: contiguous)
        uint32_t a_all[4][8];
        #pragma unroll
        for (int r = 0; r < 4; r++) {
            const uint32_t* p = Ac + (wm + lq + 8 * r) * 36 + lc * 8;
            *(uint4*)&a_all[r][0] = *(const uint4*)p;
            *(uint4*)&a_all[r][4] = *(const uint4*)(p + 4);
        }

        #pragma unroll
        for (int nt = 0; nt < 8; nt++) {
            const uint32_t* p = Bc + (wn + nt * 8 + lq) * 36 + lc * 8;
            uint32_t bbv[8];
            *(uint4*)&bbv[0] = *(const uint4*)p;
            *(uint4*)&bbv[4] = *(const uint4*)(p + 4);
            #pragma unroll
            for (int ks = 0; ks < 4; ks++) {
                uint32_t af0[4] = {a_all[0][2 * ks], a_all[1][2 * ks],
                                   a_all[0][2 * ks + 1], a_all[1][2 * ks + 1]};
                uint32_t af1[4] = {a_all[2][2 * ks], a_all[3][2 * ks],
                                   a_all[2][2 * ks + 1], a_all[3][2 * ks + 1]};
                uint32_t bf[2] = {bbv[2 * ks], bbv[2 * ks + 1]};
                mma_tf32(acc[0][nt], af0, bf);
                mma_tf32(acc[1][nt], af1, bf);
            }
        }
        __syncthreads();
    }

    #pragma unroll
    for (int mt = 0; mt < 2; mt++) {
        const int r0 = bm + wm + mt * 16 + lq;
        #pragma unroll
        for (int nt = 0; nt < 8; nt++) {
            const int c0 = bn + wn + nt * 8 + 2 * lc;
            *(float2*)(C + (size_t)r0 * N + c0) =
                make_float2(acc[mt][nt][0], acc[mt][nt][1]);
            *(float2*)(C + (size_t)(r0 + 8) * N + c0) =
                make_float2(acc[mt][nt][2], acc[mt][nt][3]);
        }
    }
}

// ---------------------------------------------------------------------------
// rope_rms_pack: gate + value_embeds mix, RoPE + RMSNorm, pre-convert to
// packed tf32: qpack (q*0.125, permd), kpack (permd), vpack (plain).
// ---------------------------------------------------------------------------
__global__ __launch_bounds__(128) void rope_rms_pack(
    const float* __restrict__ qkv, const float* __restrict__ x,
    const float* __restrict__ ve, const float* __restrict__ rc,
    const float* __restrict__ rs, const float* __restrict__ wg,
    uint32_t* __restrict__ qpack, uint32_t* __restrict__ kpack,
    uint32_t* __restrict__ vpack)
{
    const int row = blockIdx.x;
    const int t = row & (Tn - 1);
    const int b = row >> 11;
    const int warp = threadIdx.x >> 5;
    const int lane = threadIdx.x & 31;

    for (int head = warp; head < HQn + 2 * HKn; head += 4) {
        const float* p = qkv + (size_t)row * Fn + head * Dn;
        if (head < HQn + HKn) {
            float x1 = p[lane], x2 = p[lane + 32];
            float c = rc[t * (Dn / 2) + lane];
            float s = rs[t * (Dn / 2) + lane];
            float y1 = x1 * c - x2 * s;
            float y2 = x1 * s + x2 * c;
            float ss = y1 * y1 + y2 * y2;
            #pragma unroll
            for (int o = 16; o; o >>= 1) ss += __shfl_xor_sync(0xffffffffu, ss, o);
            float r = rsqrtf(ss * (1.0f / Dn) + 1e-8f);
            y1 *= r; y2 *= r;
            if (head < HQn) {
                uint32_t* qp = qpack + ((size_t)(b * HQn + head) * Tn + t) * Dn;
                qp[permd(lane)]      = f2tf32(y1 * 0.125f);
                qp[permd(lane + 32)] = f2tf32(y2 * 0.125f);
            } else {
                const int hk = head - HQn;
                uint32_t* kp = kpack + ((size_t)(b * HKn + hk) * Tn + t) * Dn;
                kp[permd(lane)]      = f2tf32(y1);
                kp[permd(lane + 32)] = f2tf32(y2);
            }
        } else {
            const int hv = head - HQn - HKn;
            float pr = (lane < GATE_CHn)
                         ? x[(size_t)row * En + lane] * wg[hv * GATE_CHn + lane]
                         : 0.f;
            #pragma unroll
            for (int o = 16; o; o >>= 1) pr += __shfl_xor_sync(0xffffffffu, pr, o);
            float gate = 3.0f / (1.0f + __expf(-pr));
            const float* vp = ve + (size_t)row * (HKn * Dn) + hv * Dn;
            uint32_t* vd = vpack + ((size_t)(b * HKn + hv) * Tn + t) * Dn;
            vd[lane]      = f2tf32(p[lane]      + gate * vp[lane]);
            vd[lane + 32] = f2tf32(p[lane + 32] + gate * vp[lane + 32]);
        }
    }
}

// ---------------------------------------------------------------------------
// Tensor-core flash attention v7: single-tf32 S (no hi/lo), pre-converted
// operands, zero cvt in mainloop, KTILE=32 cp.async double-buffered.
// Output written as tf32 bit patterns in the per-32-chunk permuted layout
// expected by gemm_tf32u.
// ---------------------------------------------------------------------------
#define QTILE 128
#define KTILE 32
#define AK_W (32 * 68)
#define AV_W (32 * 72)
#define ABUF_W (AK_W + AV_W)
#define W_PS2 (2 * ABUF_W)
#define ATTN_WORDS (W_PS2 + QTILE * 36)
#define ATTN_SMEM_BYTES (ATTN_WORDS * 4)

__global__ __launch_bounds__(256, 2) void attn_tc(
    const uint32_t* __restrict__ qpack, const uint32_t* __restrict__ kpack,
    const uint32_t* __restrict__ vpack, float* __restrict__ out)
{
    extern __shared__ uint32_t smu[];
    uint32_t* Ps = smu + W_PS2;

    const int tid = threadIdx.x;
    const int lane = tid & 31;
    const int warp = tid >> 5;
    const int q0 = blockIdx.x * QTILE;
    const int h  = blockIdx.y;
    const int bb = blockIdx.z;
    const int hk = h >> 2;
    const int row0 = bb * Tn + q0;

    const int lq = lane >> 2;
    const int lc = lane & 3;
    const int rA = warp * 16 + lq;

    const uint32_t* kp_base = kpack + (size_t)(bb * HKn + hk) * Tn * Dn;
    const uint32_t* vp_base = vpack + (size_t)(bb * HKn + hk) * Tn * Dn;

    uint32_t qA[16], qB[16];
    {
        const uint32_t* qp0 = qpack +
            ((size_t)(bb * HQn + h) * Tn + q0 + rA) * Dn + lc * 16;
        const uint32_t* qp1 = qp0 + 8 * Dn;
        #pragma unroll
        for (int u = 0; u < 4; u++) {
            *(uint4*)&qA[4 * u] = *(const uint4*)(qp0 + 4 * u);
            *(uint4*)&qB[4 * u] = *(const uint4*)(qp1 + 4 * u);
        }
    }

    float o[8][4];
    #pragma unroll
    for (int nt = 0; nt < 8; nt++)
        #pragma unroll
        for (int e = 0; e < 4; e++) o[nt][e] = 0.f;
    float lA = 0.f, lB = 0.f;

    const int kt_lo = (q0 > WINDOWn) ? ((q0 - WINDOWn) >> 5) : 0;
    const int kt_hi = (q0 + QTILE - 1) >> 5;

    auto pref = [&](int bidx, int kt) {
        const int kbase = kt * KTILE;
        uint32_t* Kd = smu + bidx * ABUF_W;
        uint32_t* Vd = Kd + AK_W;
        #pragma unroll
        for (int i = 0; i < 4; i++) {
            const int g = tid + 256 * i;
            const int reg = g >> 9;
            const int idx = g & 511;
            const int row = idx >> 4;
            const int c4 = (idx & 15) * 4;
            if (reg == 0)
                cp16(sma(Kd + row * 68 + c4),
                     kp_base + (size_t)(kbase + row) * Dn + c4);
            else
                cp16(sma(Vd + row * 72 + c4),
                     vp_base + (size_t)(kbase + row) * Dn + c4);
        }
    };

    pref(0, kt_lo);
    cp_commit();

    for (int kt = kt_lo; kt <= kt_hi; kt++) {
        const int cur = (kt - kt_lo) & 1;
        if (kt < kt_hi) {
            pref(cur ^ 1, kt + 1);
            cp_commit();
            cp_wait<1>();
        } else {
            cp_wait<0>();
        }
        __syncthreads();

        const uint32_t* Khi = smu + cur * ABUF_W;
        const uint32_t* Vv  = Khi + AK_W;
        const int k0 = kt * KTILE;
        const int swP = (warp * 2) & 3;

        #pragma unroll
        for (int nt = 0; nt < 4; nt++) {
            const int key = nt * 8 + lq;
            const uint32_t* ph = Khi + key * 68 + lc * 16;
            uint32_t kh[16];
            #pragma unroll
            for (int u = 0; u < 4; u++)
                *(uint4*)&kh[4 * u] = *(const uint4*)(ph + 4 * u);

            float s0[4] = {0.f, 0.f, 0.f, 0.f};
            float s1[4] = {0.f, 0.f, 0.f, 0.f};
            #pragma unroll
            for (int kp2 = 0; kp2 < 4; kp2++) {
                const int ka = 2 * kp2, kb = 2 * kp2 + 1;
                uint32_t afa[4] = {qA[2 * ka], qB[2 * ka],
                                   qA[2 * ka + 1], qB[2 * ka + 1]};
                uint32_t afb[4] = {qA[2 * kb], qB[2 * kb],
                                   qA[2 * kb + 1], qB[2 * kb + 1]};
                uint32_t bha[2] = {kh[2 * ka], kh[2 * ka + 1]};
                uint32_t bhb[2] = {kh[2 * kb], kh[2 * kb + 1]};
                mma_tf32(s0, afa, bha);
                mma_tf32(s1, afb, bhb);
            }

            float p[4];
            #pragma unroll
            for (int e = 0; e < 4; e++) {
                const float sv = s0[e] + s1[e];
                const int i = q0 + rA + ((e >= 2) ? 8 : 0);
                const int j = k0 + nt * 8 + 2 * lc + (e & 1);
                const bool live = (j <= i) && (j + WINDOWn >= i);
                p[e] = live ? __expf(sv - 8.0f) : 0.f;
            }
            lA += p[0] + p[1];
            lB += p[2] + p[3];

            #pragma unroll
            for (int e = 0; e < 4; e++) {
                const int col = nt * 8 + 2 * lc + (e & 1);
                const int row = rA + ((e >= 2) ? 8 : 0);
                Ps[row * 36 + (((col & 3) ^ swP) << 3) + (col >> 2)] =
                    f2tf32(p[e]);
            }
        }
        __syncwarp();

        uint32_t pA[8], pB[8];
        {
            const uint32_t* p0 = &Ps[rA * 36 + ((lc ^ swP) << 3)];
            const uint32_t* p1 = &Ps[(rA + 8) * 36 + ((lc ^ swP) << 3)];
            *(uint4*)&pA[0] = *(const uint4*)p0;
            *(uint4*)&pA[4] = *(const uint4*)(p0 + 4);
            *(uint4*)&pB[0] = *(const uint4*)p1;
            *(uint4*)&pB[4] = *(const uint4*)(p1 + 4);
        }
        #pragma unroll
        for (int ks = 0; ks < 4; ks++) {
            const int kp = ks * 8 + lc;
            uint32_t af[4] = {pA[2 * ks], pB[2 * ks],
                              pA[2 * ks + 1], pB[2 * ks + 1]};
            #pragma unroll
            for (int nt = 0; nt < 8; nt++) {
                const int d = nt * 8 + lq;
                uint32_t bf[2] = {Vv[kp * 72 + d], Vv[(kp + 4) * 72 + d]};
                mma_tf32(o[nt], af, bf);
            }
        }
        __syncthreads();
    }

    lA += __shfl_xor_sync(0xffffffffu, lA, 1);
    lA += __shfl_xor_sync(0xffffffffu, lA, 2);
    lB += __shfl_xor_sync(0xffffffffu, lB, 1);
    lB += __shfl_xor_sync(0xffffffffu, lB, 2);
    const float invA = 1.0f / lA;
    const float invB = 1.0f / lB;

    // store as tf32 bit patterns in per-32-chunk permuted layout
    #pragma unroll
    for (int nt = 0; nt < 8; nt++) {
        #pragma unroll
        for (int e = 0; e < 4; e++) {
            const int col_l = nt * 8 + 2 * lc + (e & 1);
            const int cbase = h * Dn + (col_l & 32);
            const int inner = col_l & 31;
            const int pc = (inner & 3) * 8 + (inner >> 2);
            const int row = row0 + rA + ((e >= 2) ? 8 : 0);
            const float val = o[nt][e] * ((e >= 2) ? invB : invA);
            out[(size_t)row * En + cbase + pc] =
                __uint_as_float(f2tf32(val));
        }
    }
}

// ---------------------------------------------------------------------------
extern "C" void kernel_launch(void* const* d_in, const int* in_sizes, int n_in,
                              void* d_out, int out_size)
{
    (void)in_sizes; (void)n_in; (void)out_size;
    const float* x    = (const float*)d_in[0];
    const float* ve   = (const float*)d_in[1];
    const float* rc   = (const float*)d_in[2];
    const float* rs   = (const float*)d_in[3];
    const float* wqkv = (const float*)d_in[4];
    const float* wg   = (const float*)d_in[5];
    const float* wo   = (const float*)d_in[6];
    float* out = (float*)d_out;

    float *qkv_p = nullptr, *att_p = nullptr;
    uint32_t *qp = nullptr, *kp = nullptr, *vp = nullptr;
    uint32_t *xc = nullptr, *wqc = nullptr, *woc = nullptr;
    cudaGetSymbolAddress((void**)&qkv_p, g_qkv);
    cudaGetSymbolAddress((void**)&att_p, g_att);
    cudaGetSymbolAddress((void**)&qp, g_qpack);
    cudaGetSymbolAddress((void**)&kp, g_kpack);
    cudaGetSymbolAddress((void**)&vp, g_vpack);
    cudaGetSymbolAddress((void**)&xc, g_xc);
    cudaGetSymbolAddress((void**)&wqc, g_wqc);
    cudaGetSymbolAddress((void**)&woc, g_woc);

    cudaFuncSetAttribute(gemm_tf32u,
                         cudaFuncAttributeMaxDynamicSharedMemorySize,
                         GEMM_SMEM_BYTES);
    cudaFuncSetAttribute(attn_tc,
                         cudaFuncAttributeMaxDynamicSharedMemorySize,
                         ATTN_SMEM_BYTES);

    cvt_perm<<<(Mn * En / 4 + 255) / 256, 256>>>(x, xc, Mn * En);
    cvt_perm<<<(Fn * En / 4 + 255) / 256, 256>>>(wqkv, wqc, Fn * En);
    cvt_perm<<<(En * En / 4 + 255) / 256, 256>>>(wo, woc, En * En);

    gemm_tf32u<<<dim3(Fn / 128, Mn / 128), 256, GEMM_SMEM_BYTES>>>(
        xc, wqc, qkv_p, Mn, Fn, En);
    rope_rms_pack<<<Mn, 128>>>(qkv_p, x, ve, rc, rs, wg, qp, kp, vp);
    attn_tc<<<dim3(Tn / QTILE, HQn, Bn), 256, ATTN_SMEM_BYTES>>>(
        qp, kp, vp, att_p);
    gemm_tf32u<<<dim3(En / 128, Mn / 128), 256, GEMM_SMEM_BYTES>>>(
        (const uint32_t*)att_p, woc, out, Mn, En, En);
}